// round 2
// baseline (speedup 1.0000x reference)
#include <cuda_runtime.h>
#include <math.h>

// H3TCSNetwork: x[B,7] -> 4x SiLU MLP (7->256, 3x 256->256) -> head 256->2695
// -> per-head-group scale by profiles of lam = x[:,0].
// Fully fused: one block = 32 rows, activations in smem, fp32 FFMA baseline.

#define ROWS  32
#define HID   256
#define NOUT  2695          // 77 heads * 35
#define NTHREADS 256

__device__ __forceinline__ float silu_f(float v) {
    // v * sigmoid(v)
    return v / (1.0f + expf(-v));
}

__global__ __launch_bounds__(NTHREADS)
void h3tcs_fused_kernel(const float* __restrict__ x,
                        const float* __restrict__ W0, const float* __restrict__ b0,
                        const float* __restrict__ W1, const float* __restrict__ b1,
                        const float* __restrict__ W2, const float* __restrict__ b2,
                        const float* __restrict__ W3, const float* __restrict__ b3,
                        const float* __restrict__ Wh, const float* __restrict__ bh,
                        float* __restrict__ out)
{
    __shared__ float hs[ROWS * HID];     // activation tile, 32 KB
    __shared__ float xs[ROWS * 7];
    __shared__ float sc_left[ROWS], sc_right[ROWS], sc_neck[ROWS];

    const int tid = threadIdx.x;
    const int r0  = blockIdx.x * ROWS;
    const int j   = tid;                  // this thread's hidden column

    // ---- load x tile + compute per-row profile scales ----
    if (tid < ROWS * 7) xs[tid] = x[r0 * 7 + tid];
    if (tid < ROWS) {
        float lam = x[(size_t)(r0 + tid) * 7];     // x[:,0]
        // sigmoid(5*lam/0.15)
        float s = 1.0f / (1.0f + expf(-lam * (5.0f / 0.15f)));
        sc_left[tid]  = 1.0f - s;
        sc_right[tid] = s;
        float t = lam * 5.0f;                      // lam / 0.2
        sc_neck[tid]  = expf(-t * t);
    }
    __syncthreads();

    float acc[ROWS];

    // ---- layer 0: 7 -> 256 ----
    {
        float bj = b0[j];
        #pragma unroll
        for (int r = 0; r < ROWS; r++) acc[r] = bj;
        #pragma unroll
        for (int k = 0; k < 7; k++) {
            float w = W0[k * HID + j];
            #pragma unroll
            for (int r = 0; r < ROWS; r++)
                acc[r] = fmaf(xs[r * 7 + k], w, acc[r]);
        }
        #pragma unroll
        for (int r = 0; r < ROWS; r++) hs[r * HID + j] = silu_f(acc[r]);
    }
    __syncthreads();

    // ---- layers 1..3: 256 -> 256 ----
    const float* Ws[3] = {W1, W2, W3};
    const float* bs[3] = {b1, b2, b3};
    for (int L = 0; L < 3; L++) {
        const float* __restrict__ W = Ws[L];
        float bj = bs[L][j];
        #pragma unroll
        for (int r = 0; r < ROWS; r++) acc[r] = bj;
        #pragma unroll 4
        for (int k = 0; k < HID; k++) {
            float w = W[k * HID + j];
            #pragma unroll
            for (int r = 0; r < ROWS; r++)
                acc[r] = fmaf(hs[r * HID + k], w, acc[r]);
        }
        __syncthreads();                 // everyone done READING hs
        #pragma unroll
        for (int r = 0; r < ROWS; r++) hs[r * HID + j] = silu_f(acc[r]);
        __syncthreads();                 // hs fully WRITTEN
    }

    // ---- head: 256 -> 2695, fused scale + store ----
    // 11 column tiles of 256 (last tile partial: 2695 = 10*256 + 135)
    for (int ct = 0; ct < 11; ct++) {
        int c = ct * NTHREADS + tid;
        if (c < NOUT) {
            float bj = bh[c];
            #pragma unroll
            for (int r = 0; r < ROWS; r++) acc[r] = bj;
            #pragma unroll 4
            for (int k = 0; k < HID; k++) {
                float w = Wh[k * NOUT + c];
                #pragma unroll
                for (int r = 0; r < ROWS; r++)
                    acc[r] = fmaf(hs[r * HID + k], w, acc[r]);
            }
            int head = c / 35;
            #pragma unroll
            for (int r = 0; r < ROWS; r++) {
                float sc = 1.0f;
                if      (head >= 63) sc = sc_neck[r];
                else if (head >= 49) sc = sc_right[r];
                else if (head >= 35) sc = sc_left[r];
                out[(size_t)(r0 + r) * NOUT + c] = acc[r] * sc;
            }
        }
    }
}

extern "C" void kernel_launch(void* const* d_in, const int* in_sizes, int n_in,
                              void* d_out, int out_size)
{
    const float* x  = (const float*)d_in[0];
    const float* W0 = (const float*)d_in[1];
    const float* b0 = (const float*)d_in[2];
    const float* W1 = (const float*)d_in[3];
    const float* b1 = (const float*)d_in[4];
    const float* W2 = (const float*)d_in[5];
    const float* b2 = (const float*)d_in[6];
    const float* W3 = (const float*)d_in[7];
    const float* b3 = (const float*)d_in[8];
    const float* Wh = (const float*)d_in[9];
    const float* bh = (const float*)d_in[10];
    float* out = (float*)d_out;

    int B = in_sizes[0] / 7;
    int grid = (B + ROWS - 1) / ROWS;

    h3tcs_fused_kernel<<<grid, NTHREADS>>>(x, W0, b0, W1, b1, W2, b2, W3, b3,
                                           Wh, bh, out);
}

// round 3
// speedup vs baseline: 3.2412x; 3.2412x over previous
#include <cuda_runtime.h>
#include <cuda_bf16.h>
#include <stdint.h>

// H3TCSNetwork on tensor cores: bf16-split (hi+lo) mma.sync.m16n8k16, fp32 accum.
// Block = 64 batch rows; 8 warps x (64x32) output stripes.
// Weights pre-split+packed per launch into g_pack so B-fragments are 1x LDG.128.

#define NTHREADS 256
#define MROWS    64
#define HID      256
#define NOUT     2695
#define APITCH   264                 // bf16 elements per smem row (padded: 528B)

#define PACK_HID  16384              // (256/16)*4 * 256   uint4 per hidden layer
#define PACK_HEAD 172480             // (256/16)*4 * 2695  uint4 for head
#define PACK_TOTAL (3*PACK_HID + PACK_HEAD)

__device__ uint4 g_pack[PACK_TOTAL];           // 3.5 MB scratch (allowed: __device__ global)

// ---------------- helpers ----------------
__device__ __forceinline__ uint32_t smem_u32(const void* p){
    return (uint32_t)__cvta_generic_to_shared(p);
}
// pack two floats as bf16x2, first arg in LOW half
__device__ __forceinline__ uint32_t pack2(float lo, float hi){
    uint32_t r;
    asm("cvt.rn.bf16x2.f32 %0, %1, %2;" : "=r"(r) : "f"(hi), "f"(lo));
    return r;
}
__device__ __forceinline__ void split2(float a, float b, uint32_t& hi, uint32_t& lo){
    hi = pack2(a, b);
    float ha = __uint_as_float(hi << 16);
    float hb = __uint_as_float(hi & 0xffff0000u);
    lo = pack2(a - ha, b - hb);
}
__device__ __forceinline__ float silu_f(float v){
    return __fdividef(v, 1.0f + __expf(-v));
}
__device__ __forceinline__ void ldsm_x4(uint32_t a[4], uint32_t addr){
    asm volatile("ldmatrix.sync.aligned.m8n8.x4.shared.b16 {%0,%1,%2,%3}, [%4];"
                 : "=r"(a[0]), "=r"(a[1]), "=r"(a[2]), "=r"(a[3]) : "r"(addr));
}
__device__ __forceinline__ void mma_bf16(float c[4], const uint32_t a[4],
                                         uint32_t b0, uint32_t b1){
    asm volatile("mma.sync.aligned.m16n8k16.row.col.f32.bf16.bf16.f32 "
                 "{%0,%1,%2,%3}, {%4,%5,%6,%7}, {%8,%9}, {%0,%1,%2,%3};"
                 : "+f"(c[0]), "+f"(c[1]), "+f"(c[2]), "+f"(c[3])
                 : "r"(a[0]), "r"(a[1]), "r"(a[2]), "r"(a[3]), "r"(b0), "r"(b1));
}

// ---------------- weight pack kernel ----------------
// For W (KxN row-major fp32), emit uint4 at [(s*4+q)*N + n]:
//   x = bf16x2(hi(W[16s+2q][n]),   hi(W[16s+2q+1][n]))      (B-frag b0, hi)
//   y = same with lo residuals                               (b0, lo)
//   z = bf16x2(hi(W[16s+2q+8][n]), hi(W[16s+2q+9][n]))      (b1, hi)
//   w = lo residuals                                         (b1, lo)
__global__ void pack_weights(const float* __restrict__ W1, const float* __restrict__ W2,
                             const float* __restrict__ W3, const float* __restrict__ Wh)
{
    int idx = blockIdx.x * blockDim.x + threadIdx.x;
    if (idx >= PACK_TOTAL) return;
    const float* W; uint4* P; int N; int li = idx;
    if      (idx < PACK_HID)   { W = W1; P = g_pack;               N = HID;  }
    else if (idx < 2*PACK_HID) { W = W2; P = g_pack + PACK_HID;    N = HID;  li -= PACK_HID; }
    else if (idx < 3*PACK_HID) { W = W3; P = g_pack + 2*PACK_HID;  N = HID;  li -= 2*PACK_HID; }
    else                       { W = Wh; P = g_pack + 3*PACK_HID;  N = NOUT; li -= 3*PACK_HID; }

    int n  = li % N;
    int sq = li / N;                 // s*4+q, 0..63
    int q  = sq & 3;
    int s  = sq >> 2;
    int k0 = s * 16 + q * 2;

    float a = W[(size_t)k0      * N + n];
    float b = W[(size_t)(k0+1)  * N + n];
    float c = W[(size_t)(k0+8)  * N + n];
    float d = W[(size_t)(k0+9)  * N + n];

    uint4 v;
    split2(a, b, v.x, v.y);
    split2(c, d, v.z, v.w);
    P[li] = v;
}

// ---------------- warp GEMM core ----------------
// Warp computes m64 x n32 (4 m-tiles x 4 n-tiles of m16n8), K=256 (16 ksteps).
// A: smem hi/lo bf16 planes (pitch APITCH). B: packed uint4 from g_pack.
// 3 MMAs per tile per kstep: Ahi*Bhi, Ahi*Blo, Alo*Bhi.
template<bool GUARD>
__device__ __forceinline__ void warp_gemm(const __nv_bfloat16* Ahi, const __nv_bfloat16* Alo,
                                          const uint4* __restrict__ P, int Nmat, int n0,
                                          int lane, float acc[4][4][4])
{
    const int q   = lane & 3;
    const int nl  = lane >> 2;
    const int sub = lane >> 3;
    const int rowin = (lane & 7) + (sub & 1) * 8;
    const int colin = (sub >> 1) * 8;
    uint32_t abase_hi = smem_u32(Ahi) + (uint32_t)rowin * (APITCH*2) + colin * 2;
    uint32_t abase_lo = smem_u32(Alo) + (uint32_t)rowin * (APITCH*2) + colin * 2;

    uint4 bv[4];
    #pragma unroll
    for (int nt = 0; nt < 4; nt++){
        int n = n0 + nt*8 + nl;
        if (!GUARD || n < Nmat) bv[nt] = P[(size_t)q * Nmat + n];
        else                    bv[nt] = make_uint4(0,0,0,0);
    }

    #pragma unroll 1
    for (int s = 0; s < 16; s++){
        uint4 bn[4];
        if (s < 15){
            #pragma unroll
            for (int nt = 0; nt < 4; nt++){
                int n = n0 + nt*8 + nl;
                if (!GUARD || n < Nmat) bn[nt] = P[(size_t)((s+1)*4 + q) * Nmat + n];
                else                    bn[nt] = make_uint4(0,0,0,0);
            }
        }
        uint32_t ahi[4][4], alo[4][4];
        #pragma unroll
        for (int mt = 0; mt < 4; mt++){
            uint32_t off = (uint32_t)(mt*16) * (APITCH*2) + s * 32;   // 16 cols * 2B
            ldsm_x4(ahi[mt], abase_hi + off);
            ldsm_x4(alo[mt], abase_lo + off);
        }
        #pragma unroll
        for (int mt = 0; mt < 4; mt++){
            #pragma unroll
            for (int nt = 0; nt < 4; nt++){
                mma_bf16(acc[mt][nt], ahi[mt], bv[nt].x, bv[nt].z);   // hi*hi
                mma_bf16(acc[mt][nt], ahi[mt], bv[nt].y, bv[nt].w);   // hi*lo
                mma_bf16(acc[mt][nt], alo[mt], bv[nt].x, bv[nt].z);   // lo*hi
            }
        }
        if (s < 15){
            #pragma unroll
            for (int nt = 0; nt < 4; nt++) bv[nt] = bn[nt];
        }
    }
}

__device__ __forceinline__ float hsel(int col, float l, float r, float n){
    if (col < 1225) return 1.0f;     // 35 local heads * 35
    if (col < 1715) return l;        // 14 left
    if (col < 2205) return r;        // 14 right
    return n;                        // 14 neck
}

// ---------------- main fused kernel ----------------
__global__ __launch_bounds__(NTHREADS)
void h3tcs_mma_kernel(const float* __restrict__ x,
                      const float* __restrict__ W0, const float* __restrict__ b0,
                      const float* __restrict__ b1, const float* __restrict__ b2,
                      const float* __restrict__ b3, const float* __restrict__ bh,
                      float* __restrict__ out)
{
    extern __shared__ char smem[];
    __nv_bfloat16* pA_hi = (__nv_bfloat16*)smem;
    __nv_bfloat16* pA_lo = pA_hi + MROWS*APITCH;
    __nv_bfloat16* pB_hi = pA_lo + MROWS*APITCH;
    __nv_bfloat16* pB_lo = pB_hi + MROWS*APITCH;
    float* xs     = (float*)(pB_lo + MROWS*APITCH);
    float* scl    = xs  + MROWS*7;
    float* scr    = scl + MROWS;
    float* scn    = scr + MROWS;
    float* bias_s = scn + MROWS;          // 3 * 256 floats

    const int tid  = threadIdx.x;
    const int lane = tid & 31;
    const int wid  = tid >> 5;
    const int r0   = blockIdx.x * MROWS;

    // ---- stage x tile + all hidden biases ----
    for (int i = tid; i < MROWS*7; i += NTHREADS) xs[i] = x[(size_t)r0*7 + i];
    bias_s[tid]       = b1[tid];
    bias_s[256 + tid] = b2[tid];
    bias_s[512 + tid] = b3[tid];
    __syncthreads();

    // ---- per-row head-scale profiles ----
    if (tid < MROWS){
        float lam = xs[tid*7];
        float s = 1.0f / (1.0f + __expf(lam * (-5.0f/0.15f)));
        scl[tid] = 1.0f - s;
        scr[tid] = s;
        float t = lam * 5.0f;
        scn[tid] = __expf(-t*t);
    }

    // ---- layer 0 (7 -> 256), fp32 FFMA, store split to planes A ----
    {
        int j = tid;
        float w0r[7];
        #pragma unroll
        for (int k = 0; k < 7; k++) w0r[k] = W0[k*HID + j];
        float bj = b0[j];
        for (int r = 0; r < MROWS; r++){
            float v = bj;
            #pragma unroll
            for (int k = 0; k < 7; k++) v = fmaf(xs[r*7 + k], w0r[k], v);
            v = silu_f(v);
            __nv_bfloat16 h = __float2bfloat16(v);
            pA_hi[r*APITCH + j] = h;
            pA_lo[r*APITCH + j] = __float2bfloat16(v - __bfloat162float(h));
        }
    }
    __syncthreads();

    // ---- hidden layers 1..3 (256 -> 256), ping-pong A<->B ----
    const __nv_bfloat16* ihi = pA_hi; const __nv_bfloat16* ilo = pA_lo;
    __nv_bfloat16* ohi = pB_hi;       __nv_bfloat16* olo = pB_lo;
    #pragma unroll 1
    for (int L = 0; L < 3; L++){
        float acc[4][4][4];
        #pragma unroll
        for (int a = 0; a < 4; a++)
            #pragma unroll
            for (int b = 0; b < 4; b++)
                #pragma unroll
                for (int c = 0; c < 4; c++) acc[a][b][c] = 0.0f;

        warp_gemm<false>(ihi, ilo, g_pack + L*PACK_HID, HID, wid*32, lane, acc);

        const float* bs = bias_s + L*256;
        #pragma unroll
        for (int mt = 0; mt < 4; mt++){
            int rb = mt*16 + (lane >> 2);
            #pragma unroll
            for (int nt = 0; nt < 4; nt++){
                int cb = wid*32 + nt*8 + (lane & 3)*2;
                float bb0 = bs[cb], bb1 = bs[cb+1];
                {
                    float v0 = silu_f(acc[mt][nt][0] + bb0);
                    float v1 = silu_f(acc[mt][nt][1] + bb1);
                    uint32_t h2, l2; split2(v0, v1, h2, l2);
                    *(uint32_t*)&ohi[rb*APITCH + cb] = h2;
                    *(uint32_t*)&olo[rb*APITCH + cb] = l2;
                }
                {
                    float v0 = silu_f(acc[mt][nt][2] + bb0);
                    float v1 = silu_f(acc[mt][nt][3] + bb1);
                    uint32_t h2, l2; split2(v0, v1, h2, l2);
                    *(uint32_t*)&ohi[(rb+8)*APITCH + cb] = h2;
                    *(uint32_t*)&olo[(rb+8)*APITCH + cb] = l2;
                }
            }
        }
        __syncthreads();
        // swap
        const __nv_bfloat16* th = ihi; const __nv_bfloat16* tl = ilo;
        ihi = ohi; ilo = olo;
        ohi = (__nv_bfloat16*)th; olo = (__nv_bfloat16*)tl;
    }
    // after 3 layers: final activations are in (ihi, ilo) == planes B

    // ---- head (256 -> 2695) + profile scaling + store ----
    const uint4* Ph = g_pack + 3*PACK_HID;
    #pragma unroll 1
    for (int nc = 0; nc < 11; nc++){
        int nbase = nc*256 + wid*32;
        float acc[4][4][4];
        #pragma unroll
        for (int a = 0; a < 4; a++)
            #pragma unroll
            for (int b = 0; b < 4; b++)
                #pragma unroll
                for (int c = 0; c < 4; c++) acc[a][b][c] = 0.0f;

        warp_gemm<true>(ihi, ilo, Ph, NOUT, nbase, lane, acc);

        #pragma unroll
        for (int mt = 0; mt < 4; mt++){
            int rr = mt*16 + (lane >> 2);
            float l0 = scl[rr],   rr0 = scr[rr],   n0s = scn[rr];
            float l1 = scl[rr+8], rr1 = scr[rr+8], n1s = scn[rr+8];
            #pragma unroll
            for (int nt = 0; nt < 4; nt++){
                int cb = nbase + nt*8 + (lane & 3)*2;
                if (cb < NOUT){
                    float bb0 = bh[cb];
                    float s0 = hsel(cb, l0, rr0, n0s);
                    float s1 = hsel(cb, l1, rr1, n1s);
                    out[(size_t)(r0+rr)   * NOUT + cb] = (acc[mt][nt][0] + bb0) * s0;
                    out[(size_t)(r0+rr+8) * NOUT + cb] = (acc[mt][nt][2] + bb0) * s1;
                    if (cb + 1 < NOUT){
                        float bb1 = bh[cb+1];
                        float t0 = hsel(cb+1, l0, rr0, n0s);
                        float t1 = hsel(cb+1, l1, rr1, n1s);
                        out[(size_t)(r0+rr)   * NOUT + cb+1] = (acc[mt][nt][1] + bb1) * t0;
                        out[(size_t)(r0+rr+8) * NOUT + cb+1] = (acc[mt][nt][3] + bb1) * t1;
                    }
                }
            }
        }
    }
}

// ---------------- launch ----------------
#define SMEM_BYTES (4*MROWS*APITCH*2 + MROWS*7*4 + 3*MROWS*4 + 3*256*4)

extern "C" void kernel_launch(void* const* d_in, const int* in_sizes, int n_in,
                              void* d_out, int out_size)
{
    const float* x  = (const float*)d_in[0];
    const float* W0 = (const float*)d_in[1];
    const float* b0 = (const float*)d_in[2];
    const float* W1 = (const float*)d_in[3];
    const float* b1 = (const float*)d_in[4];
    const float* W2 = (const float*)d_in[5];
    const float* b2 = (const float*)d_in[6];
    const float* W3 = (const float*)d_in[7];
    const float* b3 = (const float*)d_in[8];
    const float* Wh = (const float*)d_in[9];
    const float* bh = (const float*)d_in[10];
    float* out = (float*)d_out;

    int B = in_sizes[0] / 7;

    cudaFuncSetAttribute(h3tcs_mma_kernel,
                         cudaFuncAttributeMaxDynamicSharedMemorySize, SMEM_BYTES);

    pack_weights<<<(PACK_TOTAL + 255)/256, 256>>>(W1, W2, W3, Wh);
    h3tcs_mma_kernel<<<B / MROWS, NTHREADS, SMEM_BYTES>>>(x, W0, b0, b1, b2, b3, bh, out);
}

// round 4
// speedup vs baseline: 3.6756x; 1.1340x over previous
#include <cuda_runtime.h>
#include <cuda_bf16.h>
#include <stdint.h>

// H3TCSNetwork on tensor cores: bf16-split (hi+lo) mma.sync.m16n8k16, fp32 accum.
// R4: in-place activation planes (smem 140KB->84KB => 2 CTAs/SM), 2x4 warp grid
// (warp tile 32x64) halving redundant ldmatrix A-traffic.

#define NTHREADS 256
#define MROWS    64
#define HID      256
#define NOUT     2695
#define APITCH   264                 // bf16 elements per smem row (528 B)

#define PACK_HID  16384              // (256/16)*4 * 256   uint4 per hidden layer
#define PACK_HEAD 172480             // (256/16)*4 * 2695  uint4 for head
#define PACK_TOTAL (3*PACK_HID + PACK_HEAD)

__device__ uint4 g_pack[PACK_TOTAL];           // 3.5 MB packed-weight scratch

// ---------------- helpers ----------------
__device__ __forceinline__ uint32_t smem_u32(const void* p){
    return (uint32_t)__cvta_generic_to_shared(p);
}
__device__ __forceinline__ uint32_t pack2(float lo, float hi){
    uint32_t r;
    asm("cvt.rn.bf16x2.f32 %0, %1, %2;" : "=r"(r) : "f"(hi), "f"(lo));
    return r;
}
__device__ __forceinline__ void split2(float a, float b, uint32_t& hi, uint32_t& lo){
    hi = pack2(a, b);
    float ha = __uint_as_float(hi << 16);
    float hb = __uint_as_float(hi & 0xffff0000u);
    lo = pack2(a - ha, b - hb);
}
__device__ __forceinline__ float silu_f(float v){
    return __fdividef(v, 1.0f + __expf(-v));
}
__device__ __forceinline__ void ldsm_x4(uint32_t a[4], uint32_t addr){
    asm volatile("ldmatrix.sync.aligned.m8n8.x4.shared.b16 {%0,%1,%2,%3}, [%4];"
                 : "=r"(a[0]), "=r"(a[1]), "=r"(a[2]), "=r"(a[3]) : "r"(addr));
}
__device__ __forceinline__ void mma_bf16(float c[4], const uint32_t a[4],
                                         uint32_t b0, uint32_t b1){
    asm volatile("mma.sync.aligned.m16n8k16.row.col.f32.bf16.bf16.f32 "
                 "{%0,%1,%2,%3}, {%4,%5,%6,%7}, {%8,%9}, {%0,%1,%2,%3};"
                 : "+f"(c[0]), "+f"(c[1]), "+f"(c[2]), "+f"(c[3])
                 : "r"(a[0]), "r"(a[1]), "r"(a[2]), "r"(a[3]), "r"(b0), "r"(b1));
}

// ---------------- weight pack kernel ----------------
__global__ void pack_weights(const float* __restrict__ W1, const float* __restrict__ W2,
                             const float* __restrict__ W3, const float* __restrict__ Wh)
{
    int idx = blockIdx.x * blockDim.x + threadIdx.x;
    if (idx >= PACK_TOTAL) return;
    const float* W; uint4* P; int N; int li = idx;
    if      (idx < PACK_HID)   { W = W1; P = g_pack;               N = HID;  }
    else if (idx < 2*PACK_HID) { W = W2; P = g_pack + PACK_HID;    N = HID;  li -= PACK_HID; }
    else if (idx < 3*PACK_HID) { W = W3; P = g_pack + 2*PACK_HID;  N = HID;  li -= 2*PACK_HID; }
    else                       { W = Wh; P = g_pack + 3*PACK_HID;  N = NOUT; li -= 3*PACK_HID; }

    int n  = li % N;
    int sq = li / N;
    int q  = sq & 3;
    int s  = sq >> 2;
    int k0 = s * 16 + q * 2;

    float a = W[(size_t)k0      * N + n];
    float b = W[(size_t)(k0+1)  * N + n];
    float c = W[(size_t)(k0+8)  * N + n];
    float d = W[(size_t)(k0+9)  * N + n];

    uint4 v;
    split2(a, b, v.x, v.y);
    split2(c, d, v.z, v.w);
    P[li] = v;
}

// ---------------- warp GEMM core ----------------
// Warp tile: 32 rows (m-half wm) x 64 cols (2 m16 tiles x 8 n8 tiles), K=256.
// A: in-place smem hi/lo bf16 planes. B: packed uint4 (L2-resident).
// 3 MMAs per tile per kstep: hi*hi, hi*lo, lo*hi.
template<bool GUARD>
__device__ __forceinline__ void warp_gemm(uint32_t abase_hi, uint32_t abase_lo,
                                          const uint4* __restrict__ P, int Nmat, int n0,
                                          int lane, float acc[2][8][4])
{
    const int q  = lane & 3;
    const int nl = lane >> 2;

    #pragma unroll 1
    for (int s = 0; s < 16; s++){
        // B fragments for this kstep: 8 n-tiles, 1 x LDG.128 each
        uint4 bv[8];
        #pragma unroll
        for (int nt = 0; nt < 8; nt++){
            int n = n0 + nt*8 + nl;
            if (!GUARD || n < Nmat) bv[nt] = P[(size_t)(s*4 + q) * Nmat + n];
            else                    bv[nt] = make_uint4(0,0,0,0);
        }
        // A fragments: 2 m16 tiles x (hi,lo)
        uint32_t ahi[2][4], alo[2][4];
        #pragma unroll
        for (int mt = 0; mt < 2; mt++){
            uint32_t off = (uint32_t)(mt*16) * (APITCH*2) + s * 32;
            ldsm_x4(ahi[mt], abase_hi + off);
            ldsm_x4(alo[mt], abase_lo + off);
        }
        #pragma unroll
        for (int mt = 0; mt < 2; mt++){
            #pragma unroll
            for (int nt = 0; nt < 8; nt++){
                mma_bf16(acc[mt][nt], ahi[mt], bv[nt].x, bv[nt].z);   // hi*hi
                mma_bf16(acc[mt][nt], ahi[mt], bv[nt].y, bv[nt].w);   // hi*lo
                mma_bf16(acc[mt][nt], alo[mt], bv[nt].x, bv[nt].z);   // lo*hi
            }
        }
    }
}

__device__ __forceinline__ float hsel(int col, float l, float r, float n){
    if (col < 1225) return 1.0f;     // 35 local heads * 35
    if (col < 1715) return l;        // 14 left
    if (col < 2205) return r;        // 14 right
    return n;                        // 14 neck
}

// ---------------- main fused kernel ----------------
__global__ __launch_bounds__(NTHREADS, 2)
void h3tcs_mma_kernel(const float* __restrict__ x,
                      const float* __restrict__ W0, const float* __restrict__ b0,
                      const float* __restrict__ b1, const float* __restrict__ b2,
                      const float* __restrict__ b3, const float* __restrict__ bh,
                      float* __restrict__ out)
{
    extern __shared__ char smem[];
    __nv_bfloat16* pHi = (__nv_bfloat16*)smem;               // 64*264 bf16
    __nv_bfloat16* pLo = pHi + MROWS*APITCH;
    float* xs     = (float*)(pLo + MROWS*APITCH);            // 64*7
    float* scl    = xs  + MROWS*7;
    float* scr    = scl + MROWS;
    float* scn    = scr + MROWS;
    float* bias_s = scn + MROWS;                             // 3*256
    float* bias_h = bias_s + 3*256;                          // 2696

    const int tid  = threadIdx.x;
    const int lane = tid & 31;
    const int wid  = tid >> 5;
    const int wm   = wid & 1;            // M half: rows wm*32..wm*32+31
    const int wn   = wid >> 1;           // N quarter: cols wn*64..
    const int r0   = blockIdx.x * MROWS;

    // ---- stage x tile, biases ----
    for (int i = tid; i < MROWS*7; i += NTHREADS) xs[i] = x[(size_t)r0*7 + i];
    bias_s[tid]       = b1[tid];
    bias_s[256 + tid] = b2[tid];
    bias_s[512 + tid] = b3[tid];
    for (int i = tid; i < NOUT; i += NTHREADS) bias_h[i] = bh[i];
    __syncthreads();

    // ---- per-row head-scale profiles ----
    if (tid < MROWS){
        float lam = xs[tid*7];
        float s = 1.0f / (1.0f + __expf(lam * (-5.0f/0.15f)));
        scl[tid] = 1.0f - s;
        scr[tid] = s;
        float t = lam * 5.0f;
        scn[tid] = __expf(-t*t);
    }

    // ---- layer 0 (7 -> 256), fp32 FFMA, split-store into planes ----
    {
        int j = tid;
        float w0r[7];
        #pragma unroll
        for (int k = 0; k < 7; k++) w0r[k] = W0[k*HID + j];
        float bj = b0[j];
        for (int r = 0; r < MROWS; r++){
            float v = bj;
            #pragma unroll
            for (int k = 0; k < 7; k++) v = fmaf(xs[r*7 + k], w0r[k], v);
            v = silu_f(v);
            __nv_bfloat16 h = __float2bfloat16(v);
            pHi[r*APITCH + j] = h;
            pLo[r*APITCH + j] = __float2bfloat16(v - __bfloat162float(h));
        }
    }
    __syncthreads();

    // ldmatrix base addresses for this warp's 32-row slice
    const int sub = lane >> 3;
    const int rowin = (lane & 7) + (sub & 1) * 8;
    const int colin = (sub >> 1) * 8;
    const uint32_t abase_hi = smem_u32(pHi) +
        ((uint32_t)(wm*32 + rowin) * APITCH + colin) * 2;
    const uint32_t abase_lo = smem_u32(pLo) +
        ((uint32_t)(wm*32 + rowin) * APITCH + colin) * 2;

    // ---- hidden layers 1..3 (256 -> 256), in-place planes ----
    #pragma unroll 1
    for (int L = 0; L < 3; L++){
        float acc[2][8][4];
        #pragma unroll
        for (int a = 0; a < 2; a++)
            #pragma unroll
            for (int b = 0; b < 8; b++)
                #pragma unroll
                for (int c = 0; c < 4; c++) acc[a][b][c] = 0.0f;

        warp_gemm<false>(abase_hi, abase_lo, g_pack + L*PACK_HID, HID, wn*64, lane, acc);

        __syncthreads();            // all warps done READING planes
        const float* bs = bias_s + L*256;
        #pragma unroll
        for (int mt = 0; mt < 2; mt++){
            int rb = wm*32 + mt*16 + (lane >> 2);
            #pragma unroll
            for (int nt = 0; nt < 8; nt++){
                int cb = wn*64 + nt*8 + (lane & 3)*2;
                float bb0 = bs[cb], bb1 = bs[cb+1];
                {
                    float v0 = silu_f(acc[mt][nt][0] + bb0);
                    float v1 = silu_f(acc[mt][nt][1] + bb1);
                    uint32_t h2, l2; split2(v0, v1, h2, l2);
                    *(uint32_t*)&pHi[rb*APITCH + cb] = h2;
                    *(uint32_t*)&pLo[rb*APITCH + cb] = l2;
                }
                {
                    float v0 = silu_f(acc[mt][nt][2] + bb0);
                    float v1 = silu_f(acc[mt][nt][3] + bb1);
                    uint32_t h2, l2; split2(v0, v1, h2, l2);
                    *(uint32_t*)&pHi[(rb+8)*APITCH + cb] = h2;
                    *(uint32_t*)&pLo[(rb+8)*APITCH + cb] = l2;
                }
            }
        }
        __syncthreads();            // planes fully rewritten
    }

    // ---- head (256 -> 2695) + profile scaling + store ----
    const uint4* Ph = g_pack + 3*PACK_HID;
    #pragma unroll 1
    for (int nc = 0; nc < 11; nc++){
        int nbase = nc*256 + wn*64;
        float acc[2][8][4];
        #pragma unroll
        for (int a = 0; a < 2; a++)
            #pragma unroll
            for (int b = 0; b < 8; b++)
                #pragma unroll
                for (int c = 0; c < 4; c++) acc[a][b][c] = 0.0f;

        warp_gemm<true>(abase_hi, abase_lo, Ph, NOUT, nbase, lane, acc);

        #pragma unroll
        for (int mt = 0; mt < 2; mt++){
            int rr = wm*32 + mt*16 + (lane >> 2);
            float l0 = scl[rr],   rv0 = scr[rr],   n0s = scn[rr];
            float l1 = scl[rr+8], rv1 = scr[rr+8], n1s = scn[rr+8];
            #pragma unroll
            for (int nt = 0; nt < 8; nt++){
                int cb = nbase + nt*8 + (lane & 3)*2;
                if (cb < NOUT){
                    float bb0 = bias_h[cb];
                    float s0 = hsel(cb, l0, rv0, n0s);
                    float s1 = hsel(cb, l1, rv1, n1s);
                    out[(size_t)(r0+rr)   * NOUT + cb] = (acc[mt][nt][0] + bb0) * s0;
                    out[(size_t)(r0+rr+8) * NOUT + cb] = (acc[mt][nt][2] + bb0) * s1;
                    if (cb + 1 < NOUT){
                        float bb1 = bias_h[cb+1];
                        float t0 = hsel(cb+1, l0, rv0, n0s);
                        float t1 = hsel(cb+1, l1, rv1, n1s);
                        out[(size_t)(r0+rr)   * NOUT + cb+1] = (acc[mt][nt][1] + bb1) * t0;
                        out[(size_t)(r0+rr+8) * NOUT + cb+1] = (acc[mt][nt][3] + bb1) * t1;
                    }
                }
            }
        }
    }
}

// ---------------- launch ----------------
#define SMEM_BYTES (2*MROWS*APITCH*2 + (MROWS*7 + 3*MROWS + 3*256 + 2696)*4)

extern "C" void kernel_launch(void* const* d_in, const int* in_sizes, int n_in,
                              void* d_out, int out_size)
{
    const float* x  = (const float*)d_in[0];
    const float* W0 = (const float*)d_in[1];
    const float* b0 = (const float*)d_in[2];
    const float* W1 = (const float*)d_in[3];
    const float* b1 = (const float*)d_in[4];
    const float* W2 = (const float*)d_in[5];
    const float* b2 = (const float*)d_in[6];
    const float* W3 = (const float*)d_in[7];
    const float* b3 = (const float*)d_in[8];
    const float* Wh = (const float*)d_in[9];
    const float* bh = (const float*)d_in[10];
    float* out = (float*)d_out;

    int B = in_sizes[0] / 7;

    cudaFuncSetAttribute(h3tcs_mma_kernel,
                         cudaFuncAttributeMaxDynamicSharedMemorySize, SMEM_BYTES);

    pack_weights<<<(PACK_TOTAL + 255)/256, 256>>>(W1, W2, W3, Wh);
    h3tcs_mma_kernel<<<B / MROWS, NTHREADS, SMEM_BYTES>>>(x, W0, b0, b1, b2, b3, bh, out);
}

// round 5
// speedup vs baseline: 3.6857x; 1.0028x over previous
#include <cuda_runtime.h>
#include <cuda_bf16.h>
#include <stdint.h>

// H3TCSNetwork on tensor cores: bf16-split (hi+lo) mma.sync.m16n8k16, fp32 accum.
// R4: in-place activation planes (smem 140KB->84KB => 2 CTAs/SM), 2x4 warp grid
// (warp tile 32x64) halving redundant ldmatrix A-traffic.

#define NTHREADS 256
#define MROWS    64
#define HID      256
#define NOUT     2695
#define APITCH   264                 // bf16 elements per smem row (528 B)

#define PACK_HID  16384              // (256/16)*4 * 256   uint4 per hidden layer
#define PACK_HEAD 172480             // (256/16)*4 * 2695  uint4 for head
#define PACK_TOTAL (3*PACK_HID + PACK_HEAD)

__device__ uint4 g_pack[PACK_TOTAL];           // 3.5 MB packed-weight scratch

// ---------------- helpers ----------------
__device__ __forceinline__ uint32_t smem_u32(const void* p){
    return (uint32_t)__cvta_generic_to_shared(p);
}
__device__ __forceinline__ uint32_t pack2(float lo, float hi){
    uint32_t r;
    asm("cvt.rn.bf16x2.f32 %0, %1, %2;" : "=r"(r) : "f"(hi), "f"(lo));
    return r;
}
__device__ __forceinline__ void split2(float a, float b, uint32_t& hi, uint32_t& lo){
    hi = pack2(a, b);
    float ha = __uint_as_float(hi << 16);
    float hb = __uint_as_float(hi & 0xffff0000u);
    lo = pack2(a - ha, b - hb);
}
__device__ __forceinline__ float silu_f(float v){
    return __fdividef(v, 1.0f + __expf(-v));
}
__device__ __forceinline__ void ldsm_x4(uint32_t a[4], uint32_t addr){
    asm volatile("ldmatrix.sync.aligned.m8n8.x4.shared.b16 {%0,%1,%2,%3}, [%4];"
                 : "=r"(a[0]), "=r"(a[1]), "=r"(a[2]), "=r"(a[3]) : "r"(addr));
}
__device__ __forceinline__ void mma_bf16(float c[4], const uint32_t a[4],
                                         uint32_t b0, uint32_t b1){
    asm volatile("mma.sync.aligned.m16n8k16.row.col.f32.bf16.bf16.f32 "
                 "{%0,%1,%2,%3}, {%4,%5,%6,%7}, {%8,%9}, {%0,%1,%2,%3};"
                 : "+f"(c[0]), "+f"(c[1]), "+f"(c[2]), "+f"(c[3])
                 : "r"(a[0]), "r"(a[1]), "r"(a[2]), "r"(a[3]), "r"(b0), "r"(b1));
}

// ---------------- weight pack kernel ----------------
__global__ void pack_weights(const float* __restrict__ W1, const float* __restrict__ W2,
                             const float* __restrict__ W3, const float* __restrict__ Wh)
{
    int idx = blockIdx.x * blockDim.x + threadIdx.x;
    if (idx >= PACK_TOTAL) return;
    const float* W; uint4* P; int N; int li = idx;
    if      (idx < PACK_HID)   { W = W1; P = g_pack;               N = HID;  }
    else if (idx < 2*PACK_HID) { W = W2; P = g_pack + PACK_HID;    N = HID;  li -= PACK_HID; }
    else if (idx < 3*PACK_HID) { W = W3; P = g_pack + 2*PACK_HID;  N = HID;  li -= 2*PACK_HID; }
    else                       { W = Wh; P = g_pack + 3*PACK_HID;  N = NOUT; li -= 3*PACK_HID; }

    int n  = li % N;
    int sq = li / N;
    int q  = sq & 3;
    int s  = sq >> 2;
    int k0 = s * 16 + q * 2;

    float a = W[(size_t)k0      * N + n];
    float b = W[(size_t)(k0+1)  * N + n];
    float c = W[(size_t)(k0+8)  * N + n];
    float d = W[(size_t)(k0+9)  * N + n];

    uint4 v;
    split2(a, b, v.x, v.y);
    split2(c, d, v.z, v.w);
    P[li] = v;
}

// ---------------- warp GEMM core ----------------
// Warp tile: 32 rows (m-half wm) x 64 cols (2 m16 tiles x 8 n8 tiles), K=256.
// A: in-place smem hi/lo bf16 planes. B: packed uint4 (L2-resident).
// 3 MMAs per tile per kstep: hi*hi, hi*lo, lo*hi.
template<bool GUARD>
__device__ __forceinline__ void warp_gemm(uint32_t abase_hi, uint32_t abase_lo,
                                          const uint4* __restrict__ P, int Nmat, int n0,
                                          int lane, float acc[2][8][4])
{
    const int q  = lane & 3;
    const int nl = lane >> 2;

    #pragma unroll 1
    for (int s = 0; s < 16; s++){
        // B fragments for this kstep: 8 n-tiles, 1 x LDG.128 each
        uint4 bv[8];
        #pragma unroll
        for (int nt = 0; nt < 8; nt++){
            int n = n0 + nt*8 + nl;
            if (!GUARD || n < Nmat) bv[nt] = P[(size_t)(s*4 + q) * Nmat + n];
            else                    bv[nt] = make_uint4(0,0,0,0);
        }
        // A fragments: 2 m16 tiles x (hi,lo)
        uint32_t ahi[2][4], alo[2][4];
        #pragma unroll
        for (int mt = 0; mt < 2; mt++){
            uint32_t off = (uint32_t)(mt*16) * (APITCH*2) + s * 32;
            ldsm_x4(ahi[mt], abase_hi + off);
            ldsm_x4(alo[mt], abase_lo + off);
        }
        #pragma unroll
        for (int mt = 0; mt < 2; mt++){
            #pragma unroll
            for (int nt = 0; nt < 8; nt++){
                mma_bf16(acc[mt][nt], ahi[mt], bv[nt].x, bv[nt].z);   // hi*hi
                mma_bf16(acc[mt][nt], ahi[mt], bv[nt].y, bv[nt].w);   // hi*lo
                mma_bf16(acc[mt][nt], alo[mt], bv[nt].x, bv[nt].z);   // lo*hi
            }
        }
    }
}

__device__ __forceinline__ float hsel(int col, float l, float r, float n){
    if (col < 1225) return 1.0f;     // 35 local heads * 35
    if (col < 1715) return l;        // 14 left
    if (col < 2205) return r;        // 14 right
    return n;                        // 14 neck
}

// ---------------- main fused kernel ----------------
__global__ __launch_bounds__(NTHREADS, 2)
void h3tcs_mma_kernel(const float* __restrict__ x,
                      const float* __restrict__ W0, const float* __restrict__ b0,
                      const float* __restrict__ b1, const float* __restrict__ b2,
                      const float* __restrict__ b3, const float* __restrict__ bh,
                      float* __restrict__ out)
{
    extern __shared__ char smem[];
    __nv_bfloat16* pHi = (__nv_bfloat16*)smem;               // 64*264 bf16
    __nv_bfloat16* pLo = pHi + MROWS*APITCH;
    float* xs     = (float*)(pLo + MROWS*APITCH);            // 64*7
    float* scl    = xs  + MROWS*7;
    float* scr    = scl + MROWS;
    float* scn    = scr + MROWS;
    float* bias_s = scn + MROWS;                             // 3*256
    float* bias_h = bias_s + 3*256;                          // 2696

    const int tid  = threadIdx.x;
    const int lane = tid & 31;
    const int wid  = tid >> 5;
    const int wm   = wid & 1;            // M half: rows wm*32..wm*32+31
    const int wn   = wid >> 1;           // N quarter: cols wn*64..
    const int r0   = blockIdx.x * MROWS;

    // ---- stage x tile, biases ----
    for (int i = tid; i < MROWS*7; i += NTHREADS) xs[i] = x[(size_t)r0*7 + i];
    bias_s[tid]       = b1[tid];
    bias_s[256 + tid] = b2[tid];
    bias_s[512 + tid] = b3[tid];
    for (int i = tid; i < NOUT; i += NTHREADS) bias_h[i] = bh[i];
    __syncthreads();

    // ---- per-row head-scale profiles ----
    if (tid < MROWS){
        float lam = xs[tid*7];
        float s = 1.0f / (1.0f + __expf(lam * (-5.0f/0.15f)));
        scl[tid] = 1.0f - s;
        scr[tid] = s;
        float t = lam * 5.0f;
        scn[tid] = __expf(-t*t);
    }

    // ---- layer 0 (7 -> 256), fp32 FFMA, split-store into planes ----
    {
        int j = tid;
        float w0r[7];
        #pragma unroll
        for (int k = 0; k < 7; k++) w0r[k] = W0[k*HID + j];
        float bj = b0[j];
        for (int r = 0; r < MROWS; r++){
            float v = bj;
            #pragma unroll
            for (int k = 0; k < 7; k++) v = fmaf(xs[r*7 + k], w0r[k], v);
            v = silu_f(v);
            __nv_bfloat16 h = __float2bfloat16(v);
            pHi[r*APITCH + j] = h;
            pLo[r*APITCH + j] = __float2bfloat16(v - __bfloat162float(h));
        }
    }
    __syncthreads();

    // ldmatrix base addresses for this warp's 32-row slice
    const int sub = lane >> 3;
    const int rowin = (lane & 7) + (sub & 1) * 8;
    const int colin = (sub >> 1) * 8;
    const uint32_t abase_hi = smem_u32(pHi) +
        ((uint32_t)(wm*32 + rowin) * APITCH + colin) * 2;
    const uint32_t abase_lo = smem_u32(pLo) +
        ((uint32_t)(wm*32 + rowin) * APITCH + colin) * 2;

    // ---- hidden layers 1..3 (256 -> 256), in-place planes ----
    #pragma unroll 1
    for (int L = 0; L < 3; L++){
        float acc[2][8][4];
        #pragma unroll
        for (int a = 0; a < 2; a++)
            #pragma unroll
            for (int b = 0; b < 8; b++)
                #pragma unroll
                for (int c = 0; c < 4; c++) acc[a][b][c] = 0.0f;

        warp_gemm<false>(abase_hi, abase_lo, g_pack + L*PACK_HID, HID, wn*64, lane, acc);

        __syncthreads();            // all warps done READING planes
        const float* bs = bias_s + L*256;
        #pragma unroll
        for (int mt = 0; mt < 2; mt++){
            int rb = wm*32 + mt*16 + (lane >> 2);
            #pragma unroll
            for (int nt = 0; nt < 8; nt++){
                int cb = wn*64 + nt*8 + (lane & 3)*2;
                float bb0 = bs[cb], bb1 = bs[cb+1];
                {
                    float v0 = silu_f(acc[mt][nt][0] + bb0);
                    float v1 = silu_f(acc[mt][nt][1] + bb1);
                    uint32_t h2, l2; split2(v0, v1, h2, l2);
                    *(uint32_t*)&pHi[rb*APITCH + cb] = h2;
                    *(uint32_t*)&pLo[rb*APITCH + cb] = l2;
                }
                {
                    float v0 = silu_f(acc[mt][nt][2] + bb0);
                    float v1 = silu_f(acc[mt][nt][3] + bb1);
                    uint32_t h2, l2; split2(v0, v1, h2, l2);
                    *(uint32_t*)&pHi[(rb+8)*APITCH + cb] = h2;
                    *(uint32_t*)&pLo[(rb+8)*APITCH + cb] = l2;
                }
            }
        }
        __syncthreads();            // planes fully rewritten
    }

    // ---- head (256 -> 2695) + profile scaling + store ----
    const uint4* Ph = g_pack + 3*PACK_HID;
    #pragma unroll 1
    for (int nc = 0; nc < 11; nc++){
        int nbase = nc*256 + wn*64;
        float acc[2][8][4];
        #pragma unroll
        for (int a = 0; a < 2; a++)
            #pragma unroll
            for (int b = 0; b < 8; b++)
                #pragma unroll
                for (int c = 0; c < 4; c++) acc[a][b][c] = 0.0f;

        warp_gemm<true>(abase_hi, abase_lo, Ph, NOUT, nbase, lane, acc);

        #pragma unroll
        for (int mt = 0; mt < 2; mt++){
            int rr = wm*32 + mt*16 + (lane >> 2);
            float l0 = scl[rr],   rv0 = scr[rr],   n0s = scn[rr];
            float l1 = scl[rr+8], rv1 = scr[rr+8], n1s = scn[rr+8];
            #pragma unroll
            for (int nt = 0; nt < 8; nt++){
                int cb = nbase + nt*8 + (lane & 3)*2;
                if (cb < NOUT){
                    float bb0 = bias_h[cb];
                    float s0 = hsel(cb, l0, rv0, n0s);
                    float s1 = hsel(cb, l1, rv1, n1s);
                    out[(size_t)(r0+rr)   * NOUT + cb] = (acc[mt][nt][0] + bb0) * s0;
                    out[(size_t)(r0+rr+8) * NOUT + cb] = (acc[mt][nt][2] + bb0) * s1;
                    if (cb + 1 < NOUT){
                        float bb1 = bias_h[cb+1];
                        float t0 = hsel(cb+1, l0, rv0, n0s);
                        float t1 = hsel(cb+1, l1, rv1, n1s);
                        out[(size_t)(r0+rr)   * NOUT + cb+1] = (acc[mt][nt][1] + bb1) * t0;
                        out[(size_t)(r0+rr+8) * NOUT + cb+1] = (acc[mt][nt][3] + bb1) * t1;
                    }
                }
            }
        }
    }
}

// ---------------- launch ----------------
#define SMEM_BYTES (2*MROWS*APITCH*2 + (MROWS*7 + 3*MROWS + 3*256 + 2696)*4)

extern "C" void kernel_launch(void* const* d_in, const int* in_sizes, int n_in,
                              void* d_out, int out_size)
{
    const float* x  = (const float*)d_in[0];
    const float* W0 = (const float*)d_in[1];
    const float* b0 = (const float*)d_in[2];
    const float* W1 = (const float*)d_in[3];
    const float* b1 = (const float*)d_in[4];
    const float* W2 = (const float*)d_in[5];
    const float* b2 = (const float*)d_in[6];
    const float* W3 = (const float*)d_in[7];
    const float* b3 = (const float*)d_in[8];
    const float* Wh = (const float*)d_in[9];
    const float* bh = (const float*)d_in[10];
    float* out = (float*)d_out;

    int B = in_sizes[0] / 7;

    cudaFuncSetAttribute(h3tcs_mma_kernel,
                         cudaFuncAttributeMaxDynamicSharedMemorySize, SMEM_BYTES);

    pack_weights<<<(PACK_TOTAL + 255)/256, 256>>>(W1, W2, W3, Wh);
    h3tcs_mma_kernel<<<B / MROWS, NTHREADS, SMEM_BYTES>>>(x, W0, b0, b1, b2, b3, bh, out);
}

// round 7
// speedup vs baseline: 4.0615x; 1.1019x over previous
#include <cuda_runtime.h>
#include <cuda_bf16.h>
#include <cuda_fp16.h>
#include <stdint.h>

// H3TCSNetwork, mma.sync path (tcgen05 unavailable: harness ptxas targets sm_103).
// Hidden layers: bf16 3-term split (proven 2e-6). Head: fp16 2-term split
// (a_hi+a_lo)*b_hi  -> 2/3 the MMAs, 1/2 the B traffic, full B prefetch.

#define NTHREADS 256
#define MROWS    64
#define HID      256
#define NOUT     2695
#define APITCH   264                 // 16-bit elements per smem plane row (528 B)

#define PACK_HID   16384             // 64 * 256 uint4 per hidden layer
#define HID_U32    (3*PACK_HID*4)    // 196608 u32
#define PACK_HEAD  172480            // 64 * 2695 uint2
#define PACK_U32   (HID_U32 + PACK_HEAD*2)

__device__ uint32_t g_pack[PACK_U32];     // ~2.07 MB packed weights

// ---------------- helpers ----------------
__device__ __forceinline__ uint32_t smem_u32(const void* p){
    return (uint32_t)__cvta_generic_to_shared(p);
}
// bf16x2: first arg -> LOW half
__device__ __forceinline__ uint32_t pack2(float lo, float hi){
    uint32_t r;
    asm("cvt.rn.bf16x2.f32 %0, %1, %2;" : "=r"(r) : "f"(hi), "f"(lo));
    return r;
}
__device__ __forceinline__ void split2(float a, float b, uint32_t& hi, uint32_t& lo){
    hi = pack2(a, b);
    float ha = __uint_as_float(hi << 16);
    float hb = __uint_as_float(hi & 0xffff0000u);
    lo = pack2(a - ha, b - hb);
}
// f16x2: first arg -> LOW half
__device__ __forceinline__ uint32_t pack2h(float lo, float hi){
    uint32_t r;
    asm("cvt.rn.f16x2.f32 %0, %1, %2;" : "=r"(r) : "f"(hi), "f"(lo));
    return r;
}
__device__ __forceinline__ void split2h(float a, float b, uint32_t& hi, uint32_t& lo){
    hi = pack2h(a, b);
    float ha = __half2float(__ushort_as_half((unsigned short)(hi & 0xffffu)));
    float hb = __half2float(__ushort_as_half((unsigned short)(hi >> 16)));
    lo = pack2h(a - ha, b - hb);
}
__device__ __forceinline__ float silu_f(float v){
    return __fdividef(v, 1.0f + __expf(-v));
}
__device__ __forceinline__ void ldsm_x4(uint32_t a[4], uint32_t addr){
    asm volatile("ldmatrix.sync.aligned.m8n8.x4.shared.b16 {%0,%1,%2,%3}, [%4];"
                 : "=r"(a[0]), "=r"(a[1]), "=r"(a[2]), "=r"(a[3]) : "r"(addr));
}
__device__ __forceinline__ void mma_bf16(float c[4], const uint32_t a[4],
                                         uint32_t b0, uint32_t b1){
    asm volatile("mma.sync.aligned.m16n8k16.row.col.f32.bf16.bf16.f32 "
                 "{%0,%1,%2,%3}, {%4,%5,%6,%7}, {%8,%9}, {%0,%1,%2,%3};"
                 : "+f"(c[0]), "+f"(c[1]), "+f"(c[2]), "+f"(c[3])
                 : "r"(a[0]), "r"(a[1]), "r"(a[2]), "r"(a[3]), "r"(b0), "r"(b1));
}
__device__ __forceinline__ void mma_f16(float c[4], const uint32_t a[4],
                                        uint32_t b0, uint32_t b1){
    asm volatile("mma.sync.aligned.m16n8k16.row.col.f32.f16.f16.f32 "
                 "{%0,%1,%2,%3}, {%4,%5,%6,%7}, {%8,%9}, {%0,%1,%2,%3};"
                 : "+f"(c[0]), "+f"(c[1]), "+f"(c[2]), "+f"(c[3])
                 : "r"(a[0]), "r"(a[1]), "r"(a[2]), "r"(a[3]), "r"(b0), "r"(b1));
}

// ---------------- weight pack kernel ----------------
// Hidden (bf16 hi/lo uint4, as validated):
//   [(s*4+q)*256 + n] : x=bf16x2 hi(k0,k0+1)  y=lo  z=bf16x2 hi(k0+8,k0+9)  w=lo
// Head (fp16 single-plane uint2):
//   [(s*4+q)*2695 + n]: x=f16x2(Wh[k0][n],Wh[k0+1][n])  y=f16x2(Wh[k0+8][n],Wh[k0+9][n])
#define PACK_N (3*PACK_HID + PACK_HEAD)
__global__ void pack_weights(const float* __restrict__ W1, const float* __restrict__ W2,
                             const float* __restrict__ W3, const float* __restrict__ Wh)
{
    int idx = blockIdx.x * blockDim.x + threadIdx.x;
    if (idx >= PACK_N) return;
    if (idx < 3*PACK_HID){
        const float* W; uint4* P; int li = idx;
        if      (idx < PACK_HID)   { W = W1; P = (uint4*)g_pack; }
        else if (idx < 2*PACK_HID) { W = W2; P = (uint4*)g_pack + PACK_HID;   li -= PACK_HID; }
        else                       { W = W3; P = (uint4*)g_pack + 2*PACK_HID; li -= 2*PACK_HID; }
        int n  = li & 255;
        int sq = li >> 8;
        int q  = sq & 3, s = sq >> 2;
        int k0 = s * 16 + q * 2;
        float a = W[(size_t)k0     * HID + n];
        float b = W[(size_t)(k0+1) * HID + n];
        float c = W[(size_t)(k0+8) * HID + n];
        float d = W[(size_t)(k0+9) * HID + n];
        uint4 v;
        split2(a, b, v.x, v.y);
        split2(c, d, v.z, v.w);
        P[li] = v;
    } else {
        int li = idx - 3*PACK_HID;
        int n  = li % NOUT;
        int sq = li / NOUT;
        int q  = sq & 3, s = sq >> 2;
        int k0 = s * 16 + q * 2;
        uint2 v;
        v.x = pack2h(Wh[(size_t)k0     * NOUT + n], Wh[(size_t)(k0+1) * NOUT + n]);
        v.y = pack2h(Wh[(size_t)(k0+8) * NOUT + n], Wh[(size_t)(k0+9) * NOUT + n]);
        ((uint2*)(g_pack + HID_U32))[li] = v;
    }
}

// ---------------- hidden warp GEMM (bf16 3-term) ----------------
// Warp tile 32x64 (2 m16 x 8 n8), K=256. Term passes separated for independent
// accumulator chains: hi*hi all tiles, then hi*lo, then lo*hi.
__device__ __forceinline__ void warp_gemm_hid(uint32_t abase_hi, uint32_t abase_lo,
                                              const uint4* __restrict__ P, int n0,
                                              int lane, float acc[2][8][4])
{
    const int q  = lane & 3;
    const int nl = lane >> 2;
    #pragma unroll 1
    for (int s = 0; s < 16; s++){
        uint4 bv[8];
        #pragma unroll
        for (int nt = 0; nt < 8; nt++)
            bv[nt] = P[(size_t)(s*4 + q) * HID + n0 + nt*8 + nl];
        uint32_t ahi[2][4], alo[2][4];
        #pragma unroll
        for (int mt = 0; mt < 2; mt++){
            uint32_t off = (uint32_t)(mt*16) * (APITCH*2) + s * 32;
            ldsm_x4(ahi[mt], abase_hi + off);
            ldsm_x4(alo[mt], abase_lo + off);
        }
        #pragma unroll
        for (int mt = 0; mt < 2; mt++)
            #pragma unroll
            for (int nt = 0; nt < 8; nt++)
                mma_bf16(acc[mt][nt], ahi[mt], bv[nt].x, bv[nt].z);
        #pragma unroll
        for (int mt = 0; mt < 2; mt++)
            #pragma unroll
            for (int nt = 0; nt < 8; nt++)
                mma_bf16(acc[mt][nt], ahi[mt], bv[nt].y, bv[nt].w);
        #pragma unroll
        for (int mt = 0; mt < 2; mt++)
            #pragma unroll
            for (int nt = 0; nt < 8; nt++)
                mma_bf16(acc[mt][nt], alo[mt], bv[nt].x, bv[nt].z);
    }
}

// ---------------- head warp GEMM (fp16 2-term, B prefetched) ----------------
template<bool GUARD>
__device__ __forceinline__ void warp_gemm_head(uint32_t abase_hi, uint32_t abase_lo,
                                               const uint2* __restrict__ P, int n0,
                                               int lane, float acc[2][8][4])
{
    const int q  = lane & 3;
    const int nl = lane >> 2;
    uint2 bv[8];
    #pragma unroll
    for (int nt = 0; nt < 8; nt++){
        int n = n0 + nt*8 + nl;
        if (!GUARD || n < NOUT) bv[nt] = P[(size_t)q * NOUT + n];
        else                    bv[nt] = make_uint2(0, 0);
    }
    #pragma unroll 1
    for (int s = 0; s < 16; s++){
        uint32_t ahi[2][4], alo[2][4];
        #pragma unroll
        for (int mt = 0; mt < 2; mt++){
            uint32_t off = (uint32_t)(mt*16) * (APITCH*2) + s * 32;
            ldsm_x4(ahi[mt], abase_hi + off);
            ldsm_x4(alo[mt], abase_lo + off);
        }
        uint2 bn[8];
        if (s < 15){
            #pragma unroll
            for (int nt = 0; nt < 8; nt++){
                int n = n0 + nt*8 + nl;
                if (!GUARD || n < NOUT) bn[nt] = P[(size_t)((s+1)*4 + q) * NOUT + n];
                else                    bn[nt] = make_uint2(0, 0);
            }
        }
        #pragma unroll
        for (int mt = 0; mt < 2; mt++)
            #pragma unroll
            for (int nt = 0; nt < 8; nt++)
                mma_f16(acc[mt][nt], ahi[mt], bv[nt].x, bv[nt].y);
        #pragma unroll
        for (int mt = 0; mt < 2; mt++)
            #pragma unroll
            for (int nt = 0; nt < 8; nt++)
                mma_f16(acc[mt][nt], alo[mt], bv[nt].x, bv[nt].y);
        if (s < 15){
            #pragma unroll
            for (int nt = 0; nt < 8; nt++) bv[nt] = bn[nt];
        }
    }
}

__device__ __forceinline__ float hsel(int col, float l, float r, float n){
    if (col < 1225) return 1.0f;
    if (col < 1715) return l;
    if (col < 2205) return r;
    return n;
}

// ---------------- main fused kernel ----------------
__global__ __launch_bounds__(NTHREADS, 2)
void h3tcs_mma_kernel(const float* __restrict__ x,
                      const float* __restrict__ W0, const float* __restrict__ b0,
                      const float* __restrict__ b1, const float* __restrict__ b2,
                      const float* __restrict__ b3, const float* __restrict__ bh,
                      float* __restrict__ out)
{
    extern __shared__ char smem[];
    __nv_bfloat16* pHi = (__nv_bfloat16*)smem;               // hi plane (bf16, later fp16)
    __nv_bfloat16* pLo = pHi + MROWS*APITCH;                 // lo plane
    float* xs     = (float*)(pLo + MROWS*APITCH);
    float* scl    = xs  + MROWS*7;
    float* scr    = scl + MROWS;
    float* scn    = scr + MROWS;
    float* bias_s = scn + MROWS;                             // 3*256
    float* bias_h = bias_s + 3*256;                          // 2696

    const int tid  = threadIdx.x;
    const int lane = tid & 31;
    const int wid  = tid >> 5;
    const int wm   = wid & 1;
    const int wn   = wid >> 1;
    const int r0   = blockIdx.x * MROWS;

    for (int i = tid; i < MROWS*7; i += NTHREADS) xs[i] = x[(size_t)r0*7 + i];
    bias_s[tid]       = b1[tid];
    bias_s[256 + tid] = b2[tid];
    bias_s[512 + tid] = b3[tid];
    for (int i = tid; i < NOUT; i += NTHREADS) bias_h[i] = bh[i];
    __syncthreads();

    if (tid < MROWS){
        float lam = xs[tid*7];
        float s = 1.0f / (1.0f + __expf(lam * (-5.0f/0.15f)));
        scl[tid] = 1.0f - s;
        scr[tid] = s;
        float t = lam * 5.0f;
        scn[tid] = __expf(-t*t);
    }

    // ---- layer 0 (7 -> 256), fp32 FFMA, bf16 split store ----
    {
        int j = tid;
        float w0r[7];
        #pragma unroll
        for (int k = 0; k < 7; k++) w0r[k] = W0[k*HID + j];
        float bj = b0[j];
        for (int r = 0; r < MROWS; r++){
            float v = bj;
            #pragma unroll
            for (int k = 0; k < 7; k++) v = fmaf(xs[r*7 + k], w0r[k], v);
            v = silu_f(v);
            __nv_bfloat16 h = __float2bfloat16(v);
            pHi[r*APITCH + j] = h;
            pLo[r*APITCH + j] = __float2bfloat16(v - __bfloat162float(h));
        }
    }
    __syncthreads();

    const int sub = lane >> 3;
    const int rowin = (lane & 7) + (sub & 1) * 8;
    const int colin = (sub >> 1) * 8;
    const uint32_t abase_hi = smem_u32(pHi) +
        ((uint32_t)(wm*32 + rowin) * APITCH + colin) * 2;
    const uint32_t abase_lo = smem_u32(pLo) +
        ((uint32_t)(wm*32 + rowin) * APITCH + colin) * 2;

    // ---- hidden layers 1..3: bf16 3-term; layer 3 writes fp16 planes ----
    #pragma unroll 1
    for (int L = 0; L < 3; L++){
        float acc[2][8][4];
        #pragma unroll
        for (int a = 0; a < 2; a++)
            #pragma unroll
            for (int b = 0; b < 8; b++)
                #pragma unroll
                for (int c = 0; c < 4; c++) acc[a][b][c] = 0.0f;

        warp_gemm_hid(abase_hi, abase_lo, (const uint4*)g_pack + L*PACK_HID,
                      wn*64, lane, acc);

        __syncthreads();
        const float* bs = bias_s + L*256;
        const bool toF16 = (L == 2);
        #pragma unroll
        for (int mt = 0; mt < 2; mt++){
            int rb = wm*32 + mt*16 + (lane >> 2);
            #pragma unroll
            for (int nt = 0; nt < 8; nt++){
                int cb = wn*64 + nt*8 + (lane & 3)*2;
                float bb0 = bs[cb], bb1 = bs[cb+1];
                {
                    float v0 = silu_f(acc[mt][nt][0] + bb0);
                    float v1 = silu_f(acc[mt][nt][1] + bb1);
                    uint32_t h2, l2;
                    if (toF16) split2h(v0, v1, h2, l2); else split2(v0, v1, h2, l2);
                    *(uint32_t*)&pHi[rb*APITCH + cb] = h2;
                    *(uint32_t*)&pLo[rb*APITCH + cb] = l2;
                }
                {
                    float v0 = silu_f(acc[mt][nt][2] + bb0);
                    float v1 = silu_f(acc[mt][nt][3] + bb1);
                    uint32_t h2, l2;
                    if (toF16) split2h(v0, v1, h2, l2); else split2(v0, v1, h2, l2);
                    *(uint32_t*)&pHi[(rb+8)*APITCH + cb] = h2;
                    *(uint32_t*)&pLo[(rb+8)*APITCH + cb] = l2;
                }
            }
        }
        __syncthreads();
    }

    // ---- head (256 -> 2695), fp16 2-term, prefetched B ----
    const uint2* Ph = (const uint2*)(g_pack + HID_U32);
    #pragma unroll 1
    for (int nc = 0; nc < 11; nc++){
        int nbase = nc*256 + wn*64;
        float acc[2][8][4];
        #pragma unroll
        for (int a = 0; a < 2; a++)
            #pragma unroll
            for (int b = 0; b < 8; b++)
                #pragma unroll
                for (int c = 0; c < 4; c++) acc[a][b][c] = 0.0f;

        if (nc < 10) warp_gemm_head<false>(abase_hi, abase_lo, Ph, nbase, lane, acc);
        else         warp_gemm_head<true >(abase_hi, abase_lo, Ph, nbase, lane, acc);

        #pragma unroll
        for (int mt = 0; mt < 2; mt++){
            int rr = wm*32 + mt*16 + (lane >> 2);
            float l0 = scl[rr],   rv0 = scr[rr],   n0s = scn[rr];
            float l1 = scl[rr+8], rv1 = scr[rr+8], n1s = scn[rr+8];
            #pragma unroll
            for (int nt = 0; nt < 8; nt++){
                int cb = nbase + nt*8 + (lane & 3)*2;
                if (cb < NOUT){
                    float bb0 = bias_h[cb];
                    float s0 = hsel(cb, l0, rv0, n0s);
                    float s1 = hsel(cb, l1, rv1, n1s);
                    out[(size_t)(r0+rr)   * NOUT + cb] = (acc[mt][nt][0] + bb0) * s0;
                    out[(size_t)(r0+rr+8) * NOUT + cb] = (acc[mt][nt][2] + bb0) * s1;
                    if (cb + 1 < NOUT){
                        float bb1 = bias_h[cb+1];
                        float t0 = hsel(cb+1, l0, rv0, n0s);
                        float t1 = hsel(cb+1, l1, rv1, n1s);
                        out[(size_t)(r0+rr)   * NOUT + cb+1] = (acc[mt][nt][1] + bb1) * t0;
                        out[(size_t)(r0+rr+8) * NOUT + cb+1] = (acc[mt][nt][3] + bb1) * t1;
                    }
                }
            }
        }
    }
}

// ---------------- launch ----------------
#define SMEM_BYTES (2*MROWS*APITCH*2 + (MROWS*7 + 3*MROWS + 3*256 + 2696)*4)

extern "C" void kernel_launch(void* const* d_in, const int* in_sizes, int n_in,
                              void* d_out, int out_size)
{
    const float* x  = (const float*)d_in[0];
    const float* W0 = (const float*)d_in[1];
    const float* b0 = (const float*)d_in[2];
    const float* W1 = (const float*)d_in[3];
    const float* b1 = (const float*)d_in[4];
    const float* W2 = (const float*)d_in[5];
    const float* b2 = (const float*)d_in[6];
    const float* W3 = (const float*)d_in[7];
    const float* b3 = (const float*)d_in[8];
    const float* Wh = (const float*)d_in[9];
    const float* bh = (const float*)d_in[10];
    float* out = (float*)d_out;

    int B = in_sizes[0] / 7;

    cudaFuncSetAttribute(h3tcs_mma_kernel,
                         cudaFuncAttributeMaxDynamicSharedMemorySize, SMEM_BYTES);

    pack_weights<<<(PACK_N + 255)/256, 256>>>(W1, W2, W3, Wh);
    h3tcs_mma_kernel<<<B / MROWS, NTHREADS, SMEM_BYTES>>>(x, W0, b0, b1, b2, b3, bh, out);
}

// round 9
// speedup vs baseline: 5.4660x; 1.3458x over previous
#include <cuda_runtime.h>
#include <cuda_bf16.h>
#include <cuda_fp16.h>
#include <stdint.h>

// H3TCSNetwork, mma.sync path (tcgen05 rejected by harness ptxas: sm_103).
// Hidden layers: bf16 3-term split. Head: pure fp16 1-term, m64n32 warp tile,
// 2-deep B prefetch ring -- FIXED ordering (consume before refill).

#define NTHREADS 256
#define MROWS    64
#define HID      256
#define NOUT     2695
#define APITCH   264                 // 16-bit elems per smem plane row (528 B)

#define PACK_HID   16384             // 64 * 256 uint4 per hidden layer
#define HID_U32    (3*PACK_HID*4)
#define PACK_HEAD  172480            // 64 * 2695 uint2
#define PACK_U32   (HID_U32 + PACK_HEAD*2)

__device__ uint32_t g_pack[PACK_U32];

// ---------------- helpers ----------------
__device__ __forceinline__ uint32_t smem_u32(const void* p){
    return (uint32_t)__cvta_generic_to_shared(p);
}
__device__ __forceinline__ uint32_t pack2(float lo, float hi){
    uint32_t r;
    asm("cvt.rn.bf16x2.f32 %0, %1, %2;" : "=r"(r) : "f"(hi), "f"(lo));
    return r;
}
__device__ __forceinline__ void split2(float a, float b, uint32_t& hi, uint32_t& lo){
    hi = pack2(a, b);
    float ha = __uint_as_float(hi << 16);
    float hb = __uint_as_float(hi & 0xffff0000u);
    lo = pack2(a - ha, b - hb);
}
__device__ __forceinline__ uint32_t pack2h(float lo, float hi){
    uint32_t r;
    asm("cvt.rn.f16x2.f32 %0, %1, %2;" : "=r"(r) : "f"(hi), "f"(lo));
    return r;
}
__device__ __forceinline__ float silu_f(float v){
    return __fdividef(v, 1.0f + __expf(-v));
}
__device__ __forceinline__ void ldsm_x4(uint32_t a[4], uint32_t addr){
    asm volatile("ldmatrix.sync.aligned.m8n8.x4.shared.b16 {%0,%1,%2,%3}, [%4];"
                 : "=r"(a[0]), "=r"(a[1]), "=r"(a[2]), "=r"(a[3]) : "r"(addr));
}
__device__ __forceinline__ void mma_bf16(float c[4], const uint32_t a[4],
                                         uint32_t b0, uint32_t b1){
    asm volatile("mma.sync.aligned.m16n8k16.row.col.f32.bf16.bf16.f32 "
                 "{%0,%1,%2,%3}, {%4,%5,%6,%7}, {%8,%9}, {%0,%1,%2,%3};"
                 : "+f"(c[0]), "+f"(c[1]), "+f"(c[2]), "+f"(c[3])
                 : "r"(a[0]), "r"(a[1]), "r"(a[2]), "r"(a[3]), "r"(b0), "r"(b1));
}
__device__ __forceinline__ void mma_f16(float c[4], const uint32_t a[4],
                                        uint32_t b0, uint32_t b1){
    asm volatile("mma.sync.aligned.m16n8k16.row.col.f32.f16.f16.f32 "
                 "{%0,%1,%2,%3}, {%4,%5,%6,%7}, {%8,%9}, {%0,%1,%2,%3};"
                 : "+f"(c[0]), "+f"(c[1]), "+f"(c[2]), "+f"(c[3])
                 : "r"(a[0]), "r"(a[1]), "r"(a[2]), "r"(a[3]), "r"(b0), "r"(b1));
}

// ---------------- weight pack kernel ----------------
#define PACK_N (3*PACK_HID + PACK_HEAD)
__global__ void pack_weights(const float* __restrict__ W1, const float* __restrict__ W2,
                             const float* __restrict__ W3, const float* __restrict__ Wh)
{
    int idx = blockIdx.x * blockDim.x + threadIdx.x;
    if (idx >= PACK_N) return;
    if (idx < 3*PACK_HID){
        const float* W; uint4* P; int li = idx;
        if      (idx < PACK_HID)   { W = W1; P = (uint4*)g_pack; }
        else if (idx < 2*PACK_HID) { W = W2; P = (uint4*)g_pack + PACK_HID;   li -= PACK_HID; }
        else                       { W = W3; P = (uint4*)g_pack + 2*PACK_HID; li -= 2*PACK_HID; }
        int n  = li & 255;
        int sq = li >> 8;
        int q  = sq & 3, s = sq >> 2;
        int k0 = s * 16 + q * 2;
        float a = W[(size_t)k0     * HID + n];
        float b = W[(size_t)(k0+1) * HID + n];
        float c = W[(size_t)(k0+8) * HID + n];
        float d = W[(size_t)(k0+9) * HID + n];
        uint4 v;
        split2(a, b, v.x, v.y);
        split2(c, d, v.z, v.w);
        P[li] = v;
    } else {
        int li = idx - 3*PACK_HID;
        int n  = li % NOUT;
        int sq = li / NOUT;
        int q  = sq & 3, s = sq >> 2;
        int k0 = s * 16 + q * 2;
        uint2 v;
        v.x = pack2h(Wh[(size_t)k0     * NOUT + n], Wh[(size_t)(k0+1) * NOUT + n]);
        v.y = pack2h(Wh[(size_t)(k0+8) * NOUT + n], Wh[(size_t)(k0+9) * NOUT + n]);
        ((uint2*)(g_pack + HID_U32))[li] = v;
    }
}

// ---------------- hidden warp GEMM (bf16 3-term, 32x64 tile) ----------------
__device__ __forceinline__ void warp_gemm_hid(uint32_t abase_hi, uint32_t abase_lo,
                                              const uint4* __restrict__ P, int n0,
                                              int lane, float acc[2][8][4])
{
    const int q  = lane & 3;
    const int nl = lane >> 2;
    const uint4* p = P + (size_t)q * HID + n0 + nl;
    #pragma unroll 1
    for (int s = 0; s < 16; s++){
        uint4 bv[8];
        #pragma unroll
        for (int nt = 0; nt < 8; nt++) bv[nt] = p[nt*8];
        p += 4*HID;
        uint32_t ahi[2][4], alo[2][4];
        #pragma unroll
        for (int mt = 0; mt < 2; mt++){
            uint32_t off = (uint32_t)(mt*16) * (APITCH*2) + s * 32;
            ldsm_x4(ahi[mt], abase_hi + off);
            ldsm_x4(alo[mt], abase_lo + off);
        }
        #pragma unroll
        for (int mt = 0; mt < 2; mt++)
            #pragma unroll
            for (int nt = 0; nt < 8; nt++)
                mma_bf16(acc[mt][nt], ahi[mt], bv[nt].x, bv[nt].z);
        #pragma unroll
        for (int mt = 0; mt < 2; mt++)
            #pragma unroll
            for (int nt = 0; nt < 8; nt++)
                mma_bf16(acc[mt][nt], ahi[mt], bv[nt].y, bv[nt].w);
        #pragma unroll
        for (int mt = 0; mt < 2; mt++)
            #pragma unroll
            for (int nt = 0; nt < 8; nt++)
                mma_bf16(acc[mt][nt], alo[mt], bv[nt].x, bv[nt].z);
    }
}

// ---------------- head warp GEMM (fp16 1-term, 64x32 tile, 2-deep B ring) ----
// FIXED: each kstep does  ldsm A -> MMA(current b) -> refill b for kstep s+2.
template<bool GUARD>
__device__ __forceinline__ void warp_gemm_head(uint32_t abase,
                                               const uint2* __restrict__ P, int n0,
                                               int lane, float acc[4][4][4])
{
    const int q  = lane & 3;
    const int nl = lane >> 2;
    bool ok[4];
    #pragma unroll
    for (int nt = 0; nt < 4; nt++)
        ok[nt] = !GUARD || (n0 + nt*8 + nl) < NOUT;

    const uint2* p = P + (size_t)q * NOUT + n0 + nl;
    uint2 b0[4], b1[4];
    #pragma unroll
    for (int nt = 0; nt < 4; nt++) b0[nt] = ok[nt] ? p[nt*8] : make_uint2(0,0);
    p += 4*NOUT;
    #pragma unroll
    for (int nt = 0; nt < 4; nt++) b1[nt] = ok[nt] ? p[nt*8] : make_uint2(0,0);
    p += 4*NOUT;

    #pragma unroll 1
    for (int s = 0; s < 16; s += 2){
        // --- even kstep s: consume b0, then refill b0 for s+2 ---
        {
            uint32_t a[4][4];
            #pragma unroll
            for (int mt = 0; mt < 4; mt++)
                ldsm_x4(a[mt], abase + (uint32_t)(mt*16)*(APITCH*2) + s*32);
            #pragma unroll
            for (int mt = 0; mt < 4; mt++)
                #pragma unroll
                for (int nt = 0; nt < 4; nt++)
                    mma_f16(acc[mt][nt], a[mt], b0[nt].x, b0[nt].y);
            if (s < 14){
                #pragma unroll
                for (int nt = 0; nt < 4; nt++)
                    if (ok[nt]) b0[nt] = p[nt*8];
                p += 4*NOUT;
            }
        }
        // --- odd kstep s+1: consume b1, then refill b1 for s+3 ---
        {
            uint32_t a[4][4];
            #pragma unroll
            for (int mt = 0; mt < 4; mt++)
                ldsm_x4(a[mt], abase + (uint32_t)(mt*16)*(APITCH*2) + (s+1)*32);
            #pragma unroll
            for (int mt = 0; mt < 4; mt++)
                #pragma unroll
                for (int nt = 0; nt < 4; nt++)
                    mma_f16(acc[mt][nt], a[mt], b1[nt].x, b1[nt].y);
            if (s < 13){
                #pragma unroll
                for (int nt = 0; nt < 4; nt++)
                    if (ok[nt]) b1[nt] = p[nt*8];
                p += 4*NOUT;
            }
        }
    }
}

__device__ __forceinline__ float hsel(int col, float l, float r, float n){
    if (col < 1225) return 1.0f;
    if (col < 1715) return l;
    if (col < 2205) return r;
    return n;
}

// ---------------- main fused kernel ----------------
__global__ __launch_bounds__(NTHREADS, 2)
void h3tcs_mma_kernel(const float* __restrict__ x,
                      const float* __restrict__ W0, const float* __restrict__ b0,
                      const float* __restrict__ b1, const float* __restrict__ b2,
                      const float* __restrict__ b3, const float* __restrict__ bh,
                      float* __restrict__ out)
{
    extern __shared__ char smem[];
    __nv_bfloat16* pHi = (__nv_bfloat16*)smem;        // hi plane (bf16; fp16 after L3)
    __nv_bfloat16* pLo = pHi + MROWS*APITCH;          // lo plane (dead after L3)
    float* xs     = (float*)(pLo + MROWS*APITCH);
    float* scl    = xs  + MROWS*7;
    float* scr    = scl + MROWS;
    float* scn    = scr + MROWS;
    float* bias_s = scn + MROWS;                      // 3*256
    float* bias_h = bias_s + 3*256;                   // 2696

    const int tid  = threadIdx.x;
    const int lane = tid & 31;
    const int wid  = tid >> 5;
    const int wm   = wid & 1;
    const int wn   = wid >> 1;
    const int r0   = blockIdx.x * MROWS;

    for (int i = tid; i < MROWS*7; i += NTHREADS) xs[i] = x[(size_t)r0*7 + i];
    bias_s[tid]       = b1[tid];
    bias_s[256 + tid] = b2[tid];
    bias_s[512 + tid] = b3[tid];
    for (int i = tid; i < NOUT; i += NTHREADS) bias_h[i] = bh[i];
    __syncthreads();

    if (tid < MROWS){
        float lam = xs[tid*7];
        float s = 1.0f / (1.0f + __expf(lam * (-5.0f/0.15f)));
        scl[tid] = 1.0f - s;
        scr[tid] = s;
        float t = lam * 5.0f;
        scn[tid] = __expf(-t*t);
    }

    // ---- layer 0 (7 -> 256), fp32 FFMA, bf16 split store ----
    {
        int j = tid;
        float w0r[7];
        #pragma unroll
        for (int k = 0; k < 7; k++) w0r[k] = W0[k*HID + j];
        float bj = b0[j];
        for (int r = 0; r < MROWS; r++){
            float v = bj;
            #pragma unroll
            for (int k = 0; k < 7; k++) v = fmaf(xs[r*7 + k], w0r[k], v);
            v = silu_f(v);
            __nv_bfloat16 h = __float2bfloat16(v);
            pHi[r*APITCH + j] = h;
            pLo[r*APITCH + j] = __float2bfloat16(v - __bfloat162float(h));
        }
    }
    __syncthreads();

    const int sub = lane >> 3;
    const int rowin = (lane & 7) + (sub & 1) * 8;
    const int colin = (sub >> 1) * 8;
    // hidden (32-row slice per warp)
    const uint32_t hbase_hi = smem_u32(pHi) +
        ((uint32_t)(wm*32 + rowin) * APITCH + colin) * 2;
    const uint32_t hbase_lo = smem_u32(pLo) +
        ((uint32_t)(wm*32 + rowin) * APITCH + colin) * 2;
    // head (full 64 rows per warp)
    const uint32_t abase_head = smem_u32(pHi) +
        ((uint32_t)rowin * APITCH + colin) * 2;

    // ---- hidden layers 1..3: bf16 3-term; L3 epilogue writes fp16 (hi only) --
    #pragma unroll 1
    for (int L = 0; L < 3; L++){
        float acc[2][8][4];
        #pragma unroll
        for (int a = 0; a < 2; a++)
            #pragma unroll
            for (int b = 0; b < 8; b++)
                #pragma unroll
                for (int c = 0; c < 4; c++) acc[a][b][c] = 0.0f;

        warp_gemm_hid(hbase_hi, hbase_lo, (const uint4*)g_pack + L*PACK_HID,
                      wn*64, lane, acc);

        __syncthreads();
        const float* bs = bias_s + L*256;
        const bool toF16 = (L == 2);
        #pragma unroll
        for (int mt = 0; mt < 2; mt++){
            int rb = wm*32 + mt*16 + (lane >> 2);
            #pragma unroll
            for (int nt = 0; nt < 8; nt++){
                int cb = wn*64 + nt*8 + (lane & 3)*2;
                float bb0 = bs[cb], bb1 = bs[cb+1];
                {
                    float v0 = silu_f(acc[mt][nt][0] + bb0);
                    float v1 = silu_f(acc[mt][nt][1] + bb1);
                    if (toF16){
                        *(uint32_t*)&pHi[rb*APITCH + cb] = pack2h(v0, v1);
                    } else {
                        uint32_t h2, l2; split2(v0, v1, h2, l2);
                        *(uint32_t*)&pHi[rb*APITCH + cb] = h2;
                        *(uint32_t*)&pLo[rb*APITCH + cb] = l2;
                    }
                }
                {
                    float v0 = silu_f(acc[mt][nt][2] + bb0);
                    float v1 = silu_f(acc[mt][nt][3] + bb1);
                    if (toF16){
                        *(uint32_t*)&pHi[(rb+8)*APITCH + cb] = pack2h(v0, v1);
                    } else {
                        uint32_t h2, l2; split2(v0, v1, h2, l2);
                        *(uint32_t*)&pHi[(rb+8)*APITCH + cb] = h2;
                        *(uint32_t*)&pLo[(rb+8)*APITCH + cb] = l2;
                    }
                }
            }
        }
        __syncthreads();
    }

    // ---- head (256 -> 2695), fp16 1-term, m64n32 warp tile ----
    const uint2* Ph = (const uint2*)(g_pack + HID_U32);
    #pragma unroll 1
    for (int nc = 0; nc < 11; nc++){
        int nbase = nc*256 + wid*32;
        float acc[4][4][4];
        #pragma unroll
        for (int a = 0; a < 4; a++)
            #pragma unroll
            for (int b = 0; b < 4; b++)
                #pragma unroll
                for (int c = 0; c < 4; c++) acc[a][b][c] = 0.0f;

        if (nc < 10) warp_gemm_head<false>(abase_head, Ph, nbase, lane, acc);
        else         warp_gemm_head<true >(abase_head, Ph, nbase, lane, acc);

        #pragma unroll
        for (int mt = 0; mt < 4; mt++){
            int rr = mt*16 + (lane >> 2);
            float l0 = scl[rr],   rv0 = scr[rr],   n0s = scn[rr];
            float l1 = scl[rr+8], rv1 = scr[rr+8], n1s = scn[rr+8];
            #pragma unroll
            for (int nt = 0; nt < 4; nt++){
                int cb = nbase + nt*8 + (lane & 3)*2;
                if (cb < NOUT){
                    float bb0 = bias_h[cb];
                    float s0 = hsel(cb, l0, rv0, n0s);
                    float s1 = hsel(cb, l1, rv1, n1s);
                    out[(size_t)(r0+rr)   * NOUT + cb] = (acc[mt][nt][0] + bb0) * s0;
                    out[(size_t)(r0+rr+8) * NOUT + cb] = (acc[mt][nt][2] + bb0) * s1;
                    if (cb + 1 < NOUT){
                        float bb1 = bias_h[cb+1];
                        float t0 = hsel(cb+1, l0, rv0, n0s);
                        float t1 = hsel(cb+1, l1, rv1, n1s);
                        out[(size_t)(r0+rr)   * NOUT + cb+1] = (acc[mt][nt][1] + bb1) * t0;
                        out[(size_t)(r0+rr+8) * NOUT + cb+1] = (acc[mt][nt][3] + bb1) * t1;
                    }
                }
            }
        }
    }
}

// ---------------- launch ----------------
#define SMEM_BYTES (2*MROWS*APITCH*2 + (MROWS*7 + 3*MROWS + 3*256 + 2696)*4)

extern "C" void kernel_launch(void* const* d_in, const int* in_sizes, int n_in,
                              void* d_out, int out_size)
{
    const float* x  = (const float*)d_in[0];
    const float* W0 = (const float*)d_in[1];
    const float* b0 = (const float*)d_in[2];
    const float* W1 = (const float*)d_in[3];
    const float* b1 = (const float*)d_in[4];
    const float* W2 = (const float*)d_in[5];
    const float* b2 = (const float*)d_in[6];
    const float* W3 = (const float*)d_in[7];
    const float* b3 = (const float*)d_in[8];
    const float* Wh = (const float*)d_in[9];
    const float* bh = (const float*)d_in[10];
    float* out = (float*)d_out;

    int B = in_sizes[0] / 7;

    cudaFuncSetAttribute(h3tcs_mma_kernel,
                         cudaFuncAttributeMaxDynamicSharedMemorySize, SMEM_BYTES);

    pack_weights<<<(PACK_N + 255)/256, 256>>>(W1, W2, W3, Wh);
    h3tcs_mma_kernel<<<B / MROWS, NTHREADS, SMEM_BYTES>>>(x, W0, b0, b1, b2, b3, bh, out);
}

// round 10
// speedup vs baseline: 6.6423x; 1.2152x over previous
#include <cuda_runtime.h>
#include <cuda_bf16.h>
#include <cuda_fp16.h>
#include <stdint.h>

// H3TCSNetwork, mma.sync path (tcgen05 rejected by harness ptxas: sm_103).
// R10: ALL GEMMs pure fp16 1-term (validated ~1.2e-4 per layer), single fp16
// activation plane, unified m64n32 warp GEMM with 2-deep B prefetch ring.

#define NTHREADS 256
#define MROWS    64
#define HID      256
#define NOUT     2695
#define APITCH   264                 // fp16 elems per smem plane row (528 B)

#define PACK_HIDW  16384             // 64 * 256 uint2 per hidden layer
#define HID_U32    (3*PACK_HIDW*2)
#define PACK_HEAD  172480            // 64 * 2695 uint2
#define PACK_U32   (HID_U32 + PACK_HEAD*2)

__device__ uint32_t g_pack[PACK_U32];

// ---------------- helpers ----------------
__device__ __forceinline__ uint32_t smem_u32(const void* p){
    return (uint32_t)__cvta_generic_to_shared(p);
}
__device__ __forceinline__ uint32_t pack2h(float lo, float hi){
    uint32_t r;
    asm("cvt.rn.f16x2.f32 %0, %1, %2;" : "=r"(r) : "f"(hi), "f"(lo));
    return r;
}
__device__ __forceinline__ float silu_f(float v){
    return __fdividef(v, 1.0f + __expf(-v));
}
__device__ __forceinline__ void ldsm_x4(uint32_t a[4], uint32_t addr){
    asm volatile("ldmatrix.sync.aligned.m8n8.x4.shared.b16 {%0,%1,%2,%3}, [%4];"
                 : "=r"(a[0]), "=r"(a[1]), "=r"(a[2]), "=r"(a[3]) : "r"(addr));
}
__device__ __forceinline__ void mma_f16(float c[4], const uint32_t a[4],
                                        uint32_t b0, uint32_t b1){
    asm volatile("mma.sync.aligned.m16n8k16.row.col.f32.f16.f16.f32 "
                 "{%0,%1,%2,%3}, {%4,%5,%6,%7}, {%8,%9}, {%0,%1,%2,%3};"
                 : "+f"(c[0]), "+f"(c[1]), "+f"(c[2]), "+f"(c[3])
                 : "r"(a[0]), "r"(a[1]), "r"(a[2]), "r"(a[3]), "r"(b0), "r"(b1));
}

// ---------------- weight pack kernel ----------------
// All weights: uint2 at [(s*4+q)*N + n]:
//   x = f16x2(W[k0][n], W[k0+1][n]),  y = f16x2(W[k0+8][n], W[k0+9][n]),
//   k0 = s*16 + q*2.
#define PACK_N (3*PACK_HIDW + PACK_HEAD)
__global__ void pack_weights(const float* __restrict__ W1, const float* __restrict__ W2,
                             const float* __restrict__ W3, const float* __restrict__ Wh)
{
    int idx = blockIdx.x * blockDim.x + threadIdx.x;
    if (idx >= PACK_N) return;
    if (idx < 3*PACK_HIDW){
        const float* W; uint2* P; int li = idx;
        if      (idx < PACK_HIDW)   { W = W1; P = (uint2*)g_pack; }
        else if (idx < 2*PACK_HIDW) { W = W2; P = (uint2*)g_pack + PACK_HIDW;   li -= PACK_HIDW; }
        else                        { W = W3; P = (uint2*)g_pack + 2*PACK_HIDW; li -= 2*PACK_HIDW; }
        int n  = li & 255;
        int sq = li >> 8;
        int q  = sq & 3, s = sq >> 2;
        int k0 = s * 16 + q * 2;
        uint2 v;
        v.x = pack2h(W[(size_t)k0     * HID + n], W[(size_t)(k0+1) * HID + n]);
        v.y = pack2h(W[(size_t)(k0+8) * HID + n], W[(size_t)(k0+9) * HID + n]);
        P[li] = v;
    } else {
        int li = idx - 3*PACK_HIDW;
        int n  = li % NOUT;
        int sq = li / NOUT;
        int q  = sq & 3, s = sq >> 2;
        int k0 = s * 16 + q * 2;
        uint2 v;
        v.x = pack2h(Wh[(size_t)k0     * NOUT + n], Wh[(size_t)(k0+1) * NOUT + n]);
        v.y = pack2h(Wh[(size_t)(k0+8) * NOUT + n], Wh[(size_t)(k0+9) * NOUT + n]);
        ((uint2*)(g_pack + HID_U32))[li] = v;
    }
}

// ---------------- unified warp GEMM (fp16 1-term, 64x32 tile, 2-deep ring) ---
// Each kstep: ldsm A -> MMA(current b) -> refill b for kstep s+2.
template<bool GUARD>
__device__ __forceinline__ void warp_gemm_f16(uint32_t abase,
                                              const uint2* __restrict__ P, int Nmat,
                                              int n0, int lane, float acc[4][4][4])
{
    const int q  = lane & 3;
    const int nl = lane >> 2;
    bool ok[4];
    #pragma unroll
    for (int nt = 0; nt < 4; nt++)
        ok[nt] = !GUARD || (n0 + nt*8 + nl) < Nmat;

    const uint2* p = P + (size_t)q * Nmat + n0 + nl;
    uint2 b0[4], b1[4];
    #pragma unroll
    for (int nt = 0; nt < 4; nt++) b0[nt] = ok[nt] ? p[nt*8] : make_uint2(0,0);
    p += 4*Nmat;
    #pragma unroll
    for (int nt = 0; nt < 4; nt++) b1[nt] = ok[nt] ? p[nt*8] : make_uint2(0,0);
    p += 4*Nmat;

    #pragma unroll 1
    for (int s = 0; s < 16; s += 2){
        {
            uint32_t a[4][4];
            #pragma unroll
            for (int mt = 0; mt < 4; mt++)
                ldsm_x4(a[mt], abase + (uint32_t)(mt*16)*(APITCH*2) + s*32);
            #pragma unroll
            for (int mt = 0; mt < 4; mt++)
                #pragma unroll
                for (int nt = 0; nt < 4; nt++)
                    mma_f16(acc[mt][nt], a[mt], b0[nt].x, b0[nt].y);
            if (s < 14){
                #pragma unroll
                for (int nt = 0; nt < 4; nt++)
                    if (ok[nt]) b0[nt] = p[nt*8];
                p += 4*Nmat;
            }
        }
        {
            uint32_t a[4][4];
            #pragma unroll
            for (int mt = 0; mt < 4; mt++)
                ldsm_x4(a[mt], abase + (uint32_t)(mt*16)*(APITCH*2) + (s+1)*32);
            #pragma unroll
            for (int mt = 0; mt < 4; mt++)
                #pragma unroll
                for (int nt = 0; nt < 4; nt++)
                    mma_f16(acc[mt][nt], a[mt], b1[nt].x, b1[nt].y);
            if (s < 13){
                #pragma unroll
                for (int nt = 0; nt < 4; nt++)
                    if (ok[nt]) b1[nt] = p[nt*8];
                p += 4*Nmat;
            }
        }
    }
}

__device__ __forceinline__ float hsel(int col, float l, float r, float n){
    if (col < 1225) return 1.0f;
    if (col < 1715) return l;
    if (col < 2205) return r;
    return n;
}

// ---------------- main fused kernel ----------------
__global__ __launch_bounds__(NTHREADS, 2)
void h3tcs_mma_kernel(const float* __restrict__ x,
                      const float* __restrict__ W0, const float* __restrict__ b0,
                      const float* __restrict__ b1, const float* __restrict__ b2,
                      const float* __restrict__ b3, const float* __restrict__ bh,
                      float* __restrict__ out)
{
    extern __shared__ char smem[];
    __half* pA    = (__half*)smem;                    // single fp16 plane
    float* xs     = (float*)(pA + MROWS*APITCH);
    float* scl    = xs  + MROWS*7;
    float* scr    = scl + MROWS;
    float* scn    = scr + MROWS;
    float* bias_s = scn + MROWS;                      // 3*256
    float* bias_h = bias_s + 3*256;                   // 2696

    const int tid  = threadIdx.x;
    const int lane = tid & 31;
    const int wid  = tid >> 5;
    const int r0   = blockIdx.x * MROWS;

    for (int i = tid; i < MROWS*7; i += NTHREADS) xs[i] = x[(size_t)r0*7 + i];
    bias_s[tid]       = b1[tid];
    bias_s[256 + tid] = b2[tid];
    bias_s[512 + tid] = b3[tid];
    for (int i = tid; i < NOUT; i += NTHREADS) bias_h[i] = bh[i];
    __syncthreads();

    if (tid < MROWS){
        float lam = xs[tid*7];
        float s = 1.0f / (1.0f + __expf(lam * (-5.0f/0.15f)));
        scl[tid] = 1.0f - s;
        scr[tid] = s;
        float t = lam * 5.0f;
        scn[tid] = __expf(-t*t);
    }

    // ---- layer 0 (7 -> 256), fp32 FFMA, fp16 store ----
    {
        int j = tid;
        float w0r[7];
        #pragma unroll
        for (int k = 0; k < 7; k++) w0r[k] = W0[k*HID + j];
        float bj = b0[j];
        for (int r = 0; r < MROWS; r++){
            float v = bj;
            #pragma unroll
            for (int k = 0; k < 7; k++) v = fmaf(xs[r*7 + k], w0r[k], v);
            pA[r*APITCH + j] = __float2half(silu_f(v));
        }
    }
    __syncthreads();

    const int sub = lane >> 3;
    const int rowin = (lane & 7) + (sub & 1) * 8;
    const int colin = (sub >> 1) * 8;
    const uint32_t abase = smem_u32(pA) + ((uint32_t)rowin * APITCH + colin) * 2;

    // ---- hidden layers 1..3: fp16 1-term, m64n32 per warp ----
    #pragma unroll 1
    for (int L = 0; L < 3; L++){
        float acc[4][4][4];
        #pragma unroll
        for (int a = 0; a < 4; a++)
            #pragma unroll
            for (int b = 0; b < 4; b++)
                #pragma unroll
                for (int c = 0; c < 4; c++) acc[a][b][c] = 0.0f;

        warp_gemm_f16<false>(abase, (const uint2*)g_pack + L*PACK_HIDW, HID,
                             wid*32, lane, acc);

        __syncthreads();            // all warps done READING plane
        const float* bs = bias_s + L*256;
        #pragma unroll
        for (int mt = 0; mt < 4; mt++){
            int rb = mt*16 + (lane >> 2);
            #pragma unroll
            for (int nt = 0; nt < 4; nt++){
                int cb = wid*32 + nt*8 + (lane & 3)*2;
                float bb0 = bs[cb], bb1 = bs[cb+1];
                float v0 = silu_f(acc[mt][nt][0] + bb0);
                float v1 = silu_f(acc[mt][nt][1] + bb1);
                *(uint32_t*)&pA[rb*APITCH + cb] = pack2h(v0, v1);
                float v2 = silu_f(acc[mt][nt][2] + bb0);
                float v3 = silu_f(acc[mt][nt][3] + bb1);
                *(uint32_t*)&pA[(rb+8)*APITCH + cb] = pack2h(v2, v3);
            }
        }
        __syncthreads();            // plane fully rewritten
    }

    // ---- head (256 -> 2695), fp16 1-term ----
    const uint2* Ph = (const uint2*)(g_pack + HID_U32);
    #pragma unroll 1
    for (int nc = 0; nc < 11; nc++){
        int nbase = nc*256 + wid*32;
        float acc[4][4][4];
        #pragma unroll
        for (int a = 0; a < 4; a++)
            #pragma unroll
            for (int b = 0; b < 4; b++)
                #pragma unroll
                for (int c = 0; c < 4; c++) acc[a][b][c] = 0.0f;

        if (nc < 10) warp_gemm_f16<false>(abase, Ph, NOUT, nbase, lane, acc);
        else         warp_gemm_f16<true >(abase, Ph, NOUT, nbase, lane, acc);

        #pragma unroll
        for (int mt = 0; mt < 4; mt++){
            int rr = mt*16 + (lane >> 2);
            float l0 = scl[rr],   rv0 = scr[rr],   n0s = scn[rr];
            float l1 = scl[rr+8], rv1 = scr[rr+8], n1s = scn[rr+8];
            #pragma unroll
            for (int nt = 0; nt < 4; nt++){
                int cb = nbase + nt*8 + (lane & 3)*2;
                if (cb < NOUT){
                    float bb0 = bias_h[cb];
                    float s0 = hsel(cb, l0, rv0, n0s);
                    float s1 = hsel(cb, l1, rv1, n1s);
                    out[(size_t)(r0+rr)   * NOUT + cb] = (acc[mt][nt][0] + bb0) * s0;
                    out[(size_t)(r0+rr+8) * NOUT + cb] = (acc[mt][nt][2] + bb0) * s1;
                    if (cb + 1 < NOUT){
                        float bb1 = bias_h[cb+1];
                        float t0 = hsel(cb+1, l0, rv0, n0s);
                        float t1 = hsel(cb+1, l1, rv1, n1s);
                        out[(size_t)(r0+rr)   * NOUT + cb+1] = (acc[mt][nt][1] + bb1) * t0;
                        out[(size_t)(r0+rr+8) * NOUT + cb+1] = (acc[mt][nt][3] + bb1) * t1;
                    }
                }
            }
        }
    }
}

// ---------------- launch ----------------
#define SMEM_BYTES (MROWS*APITCH*2 + (MROWS*7 + 3*MROWS + 3*256 + 2696)*4)

extern "C" void kernel_launch(void* const* d_in, const int* in_sizes, int n_in,
                              void* d_out, int out_size)
{
    const float* x  = (const float*)d_in[0];
    const float* W0 = (const float*)d_in[1];
    const float* b0 = (const float*)d_in[2];
    const float* W1 = (const float*)d_in[3];
    const float* b1 = (const float*)d_in[4];
    const float* W2 = (const float*)d_in[5];
    const float* b2 = (const float*)d_in[6];
    const float* W3 = (const float*)d_in[7];
    const float* b3 = (const float*)d_in[8];
    const float* Wh = (const float*)d_in[9];
    const float* bh = (const float*)d_in[10];
    float* out = (float*)d_out;

    int B = in_sizes[0] / 7;

    cudaFuncSetAttribute(h3tcs_mma_kernel,
                         cudaFuncAttributeMaxDynamicSharedMemorySize, SMEM_BYTES);

    pack_weights<<<(PACK_N + 255)/256, 256>>>(W1, W2, W3, Wh);
    h3tcs_mma_kernel<<<B / MROWS, NTHREADS, SMEM_BYTES>>>(x, W0, b0, b1, b2, b3, bh, out);
}